// round 7
// baseline (speedup 1.0000x reference)
#include <cuda_runtime.h>
#include <math.h>
#include <stdint.h>

#define B 8
#define D 256
#define NN 1024
#define MM 1024
#define H 8
#define KD 64
#define VD 64
#define KVR 128

// smem (floats): 4 stages x (K 2048 | V 2048) = 16384 | Xs/Qsm @16384
#define XS_OFF 16384
#define XSP 40              // Xs [256][40]
#define QSM_OFF 16384
#define QSP 34              // Qsm [512][34]
#define SMEM_FLOATS (QSM_OFF + 512 * QSP)   // 33792
#define SMEM_BYTES (SMEM_FLOATS * 4)
#define OSS 524             // epilogue Os [32][OSS] @ sm+0

#define QSCALE 0.1803368801f   // 0.125 * log2(e)

__device__ float g_WkvT[KVR * D];
__device__ float g_WqP[512 * D];         // Wq A-fragment packed, pre-scaled tf32
__device__ float g_K[B * 32 * 8 * 256];  // K fragment-packed per 32-m chunk
__device__ float g_V[B * 32 * 4 * 512];  // V fragment-packed per 32-m chunk
__device__ float g_WoP[D * 512];         // Wo A-fragment packed, tf32

__device__ __forceinline__ float to_tf32(float x) {
    uint32_t u;
    asm("cvt.rna.tf32.f32 %0, %1;" : "=r"(u) : "f"(x));
    return __uint_as_float(u);
}
__device__ __forceinline__ float ex2(float x) {
    float r; asm("ex2.approx.f32 %0, %1;" : "=f"(r) : "f"(x)); return r;
}
__device__ __forceinline__ float rcp(float x) {
    float r; asm("rcp.approx.f32 %0, %1;" : "=f"(r) : "f"(x)); return r;
}
__device__ __forceinline__ void mma8(float* c, const float* a, const float* b) {
    asm volatile(
        "mma.sync.aligned.m16n8k8.row.col.f32.tf32.tf32.f32 "
        "{%0,%1,%2,%3}, {%4,%5,%6,%7}, {%8,%9}, {%0,%1,%2,%3};\n"
        : "+f"(c[0]), "+f"(c[1]), "+f"(c[2]), "+f"(c[3])
        : "r"(__float_as_uint(a[0])), "r"(__float_as_uint(a[1])),
          "r"(__float_as_uint(a[2])), "r"(__float_as_uint(a[3])),
          "r"(__float_as_uint(b[0])), "r"(__float_as_uint(b[1])));
}
__device__ __forceinline__ void cp16(uint32_t dst, const float* src) {
    asm volatile("cp.async.cg.shared.global [%0], [%1], 16;\n"
                 :: "r"(dst), "l"(src));
}
#define CP_COMMIT() asm volatile("cp.async.commit_group;\n" ::)
#define CP_WAIT(n)  asm volatile("cp.async.wait_group %0;\n" :: "n"(n))

// ---------------- kernel 0: pack weights ----------------
__global__ void pack_weights(const float* __restrict__ Wq,
                             const float* __restrict__ Wk,
                             const float* __restrict__ Wv,
                             const float* __restrict__ Wo) {
    int i = blockIdx.x * blockDim.x + threadIdx.x;
    if (i < KVR * D) {
        int r = i / D, d = i % D;
        g_WkvT[i] = (r < 64) ? Wk[d * KD + r] : Wv[d * VD + (r - 64)];
    }
    if (i < 512 * D) {   // WqP: [w16][kc32][mi2][lane32][e4]
        int e = i & 3, ln = (i >> 2) & 31, mi = (i >> 7) & 1;
        int kc = (i >> 8) & 31, w = (i >> 13) & 15;
        int gid = ln >> 2, tig = ln & 3;
        int rk = w * 32 + mi * 16 + gid + 8 * (e & 1);
        int d = kc * 8 + tig + 4 * (e >> 1);
        int kq = rk >> 3, h = rk & 7;
        g_WqP[i] = to_tf32(Wq[h * (D * KD) + d * KD + kq] * QSCALE);
    }
    if (i < D * 512) {   // WoP: [wg16][vh0c16][kc4][lane32][f4]
        int f = i & 3, ln = (i >> 2) & 31, kc = (i >> 7) & 3;
        int vh0c = (i >> 9) & 15, wg = i >> 13;
        int gid = ln >> 2, tig = ln & 3;
        int d = wg * 16 + gid + 8 * (f & 1);
        int vh = vh0c * 32 + kc * 8 + tig + 4 * (f >> 1);
        g_WoP[i] = to_tf32(Wo[d * 512 + vh]);
    }
}

// ---------------- kernel 1: K/V projection GEMM ----------------
__global__ void __launch_bounds__(256) proj_kv(const float* __restrict__ X) {
    const int b = blockIdx.z, n0 = blockIdx.x * 128;
    const float* A = g_WkvT;
    const float* Xb = X + b * (D * NN);

    __shared__ float As[16 * 136];
    __shared__ float Xs[16 * 128];

    float acc[8][8] = {};
    const int tid = threadIdx.x;
    const int tr = tid >> 4, tn = tid & 15;

    for (int dc = 0; dc < D; dc += 16) {
#pragma unroll
        for (int i = 0; i < 8; i++) {
            int idx = tid + i * 256;
            int rr = idx >> 4, c = idx & 15;
            As[c * 136 + rr] = A[rr * D + dc + c];
        }
#pragma unroll
        for (int i = 0; i < 8; i++) {
            int idx = tid + i * 256;
            int c = idx >> 7, nn = idx & 127;
            Xs[c * 128 + nn] = Xb[(dc + c) * NN + n0 + nn];
        }
        __syncthreads();
#pragma unroll
        for (int c = 0; c < 16; c++) {
            float4 a0 = *(const float4*)&As[c * 136 + tr * 4];
            float4 a1 = *(const float4*)&As[c * 136 + 64 + tr * 4];
            float4 x0 = *(const float4*)&Xs[c * 128 + tn * 4];
            float4 x1 = *(const float4*)&Xs[c * 128 + 64 + tn * 4];
            float ra[8] = {a0.x, a0.y, a0.z, a0.w, a1.x, a1.y, a1.z, a1.w};
            float rx[8] = {x0.x, x0.y, x0.z, x0.w, x1.x, x1.y, x1.z, x1.w};
#pragma unroll
            for (int i = 0; i < 8; i++)
#pragma unroll
                for (int j = 0; j < 8; j++) acc[i][j] += ra[i] * rx[j];
        }
        __syncthreads();
    }

#pragma unroll
    for (int i = 0; i < 8; i++) {
        int r = tr * 4 + (i & 3) + (i >> 2) * 64;
#pragma unroll
        for (int j = 0; j < 8; j++) {
            int n = n0 + tn * 4 + (j & 3) + (j >> 2) * 64;
            float v = to_tf32(acc[i][j]);
            if (r < 64) {
                int k = r, m = n;
                int addr = (((b * 32 + (m >> 5)) * 8 + (k >> 3)) << 8)
                         + (((m >> 4) & 1) << 7)
                         + (((m & 7) * 4 + (k & 3)) << 2)
                         + (((k >> 2) & 1) << 1) + ((m >> 3) & 1);
                g_K[addr] = v;
            } else {
                int vv = r - 64, m = n, mc = m & 31;
                int addr = (((b * 32 + (m >> 5)) * 4 + (mc >> 3)) << 9)
                         + ((vv >> 4) << 7)
                         + (((vv & 7) * 4 + (mc & 3)) << 2)
                         + (((mc >> 2) & 1) << 1) + ((vv >> 3) & 1);
                g_V[addr] = v;
            }
        }
    }
}

// ---------------- kernel 2: fused main (Q-proj prologue + attention) ----------------
__global__ void __launch_bounds__(512, 1) mqa_main(const float* __restrict__ x,
                                                   float* __restrict__ out) {
    extern __shared__ float sm[];

    const int b = blockIdx.y;
    const int n0 = blockIdx.x * 32;
    const int tid = threadIdx.x;
    const int lane = tid & 31;
    const int wgrp = tid >> 5;   // 0..15
    const int gid = lane >> 2;
    const int tig = lane & 3;

    const float* Kg = g_K + b * 65536;
    const float* Vg = g_V + b * 65536;

    // issue first 3 K/V stages via cp.async
    const uint32_t smem_u32 = (uint32_t)__cvta_generic_to_shared(sm);
#pragma unroll
    for (int s = 0; s < 3; s++) {
        uint32_t dk = smem_u32 + (s * 4096 + tid * 4) * 4;
        cp16(dk, Kg + s * 2048 + tid * 4);
        cp16(dk + 2048 * 4, Vg + s * 2048 + tid * 4);
        CP_COMMIT();
    }

    // ---- prologue: Q projection via MMA ----
    float Qreg[8][4];
    {
        float* Xs = sm + XS_OFF;   // [256][40]
        const float* Xb = x + b * (D * NN);
#pragma unroll
        for (int i = 0; i < 16; i++) {
            int idx = tid + i * 512;
            int d = idx >> 5, n = idx & 31;
            Xs[d * XSP + n] = to_tf32(Xb[d * NN + n0 + n]);
        }
        __syncthreads();

        float qa[2][4][4] = {};
        const float* WqPw = g_WqP + wgrp * 8192;
#pragma unroll 4
        for (int kc = 0; kc < 32; kc++) {
            float4 a0 = *(const float4*)&WqPw[kc * 256 + lane * 4];
            float4 a1 = *(const float4*)&WqPw[kc * 256 + 128 + lane * 4];
            float bf[4][2];
#pragma unroll
            for (int ni = 0; ni < 4; ni++) {
                bf[ni][0] = Xs[(kc * 8 + tig) * XSP + ni * 8 + gid];
                bf[ni][1] = Xs[(kc * 8 + tig + 4) * XSP + ni * 8 + gid];
            }
#pragma unroll
            for (int ni = 0; ni < 4; ni++) {
                mma8(qa[0][ni], &a0.x, bf[ni]);
                mma8(qa[1][ni], &a1.x, bf[ni]);
            }
        }
        __syncthreads();   // Xs reads done before Qsm overwrites

        float* Qsm = sm + QSM_OFF;   // [512][34]
#pragma unroll
        for (int mi = 0; mi < 2; mi++)
#pragma unroll
            for (int ni = 0; ni < 4; ni++) {
                int row = wgrp * 32 + mi * 16 + gid;
                int col = ni * 8 + tig * 2;
                *(float2*)&Qsm[row * QSP + col] =
                    make_float2(to_tf32(qa[mi][ni][0]), to_tf32(qa[mi][ni][1]));
                *(float2*)&Qsm[(row + 8) * QSP + col] =
                    make_float2(to_tf32(qa[mi][ni][2]), to_tf32(qa[mi][ni][3]));
            }
        __syncthreads();

        // load persistent Q B-fragments: col = wgrp*16 + gid + 8*ni, k = kc*8+tig+4e
#pragma unroll
        for (int kc = 0; kc < 8; kc++)
#pragma unroll
            for (int ni = 0; ni < 2; ni++)
#pragma unroll
                for (int e = 0; e < 2; e++) {
                    int k = kc * 8 + tig + 4 * e;
                    Qreg[kc][ni * 2 + e] = Qsm[(k * 8 + gid) * QSP + wgrp * 2 + ni];
                }
    }

    float Oacc[4][2][4] = {};
    const int src = tig * 4 + (gid >> 1);
    const bool og = gid & 1;

    for (int mch = 0; mch < 32; mch++) {
        CP_WAIT(2);
        __syncthreads();

        // issue stage mch+3
        if (mch + 3 < 32) {
            int s = (mch + 3) & 3;
            uint32_t dk = smem_u32 + (s * 4096 + tid * 4) * 4;
            cp16(dk, Kg + (mch + 3) * 2048 + tid * 4);
            cp16(dk + 2048 * 4, Vg + (mch + 3) * 2048 + tid * 4);
        }
        CP_COMMIT();

        const float* Ks = sm + (mch & 3) * 4096;
        const float* Vs = Ks + 2048;

        // ---- phase 1: logits (Q from registers) ----
        float c1[2][2][4] = {};
#pragma unroll
        for (int kc = 0; kc < 8; kc++) {
            float4 a0 = *(const float4*)&Ks[kc * 256 + lane * 4];
            float4 a1 = *(const float4*)&Ks[kc * 256 + 128 + lane * 4];
            mma8(c1[0][0], &a0.x, &Qreg[kc][0]);
            mma8(c1[0][1], &a0.x, &Qreg[kc][2]);
            mma8(c1[1][0], &a1.x, &Qreg[kc][0]);
            mma8(c1[1][1], &a1.x, &Qreg[kc][2]);
        }

        // ---- softmax over heads ----
#pragma unroll
        for (int mi = 0; mi < 2; mi++)
#pragma unroll
            for (int ni = 0; ni < 2; ni++) {
                float* cc = c1[mi][ni];
                float e0 = ex2(cc[0]), e1 = ex2(cc[1]);
                float sa = e0 + e1;
                sa += __shfl_xor_sync(0xffffffffu, sa, 1);
                sa += __shfl_xor_sync(0xffffffffu, sa, 2);
                float ra = rcp(sa);
                cc[0] = to_tf32(e0 * ra); cc[1] = to_tf32(e1 * ra);
                float e2 = ex2(cc[2]), e3 = ex2(cc[3]);
                float sb = e2 + e3;
                sb += __shfl_xor_sync(0xffffffffu, sb, 1);
                sb += __shfl_xor_sync(0xffffffffu, sb, 2);
                float rb = rcp(sb);
                cc[2] = to_tf32(e2 * rb); cc[3] = to_tf32(e3 * rb);
            }

        // ---- phase 3: transpose (per kc3) + O += V @ attn ----
#pragma unroll
        for (int kc3 = 0; kc3 < 4; kc3++) {
            const int mi = kc3 >> 1, p = kc3 & 1;
            float bt[2][2];
#pragma unroll
            for (int ni = 0; ni < 2; ni++) {
                float lo = c1[mi][ni][2 * p], hi = c1[mi][ni][2 * p + 1];
                float t0 = __shfl_sync(0xffffffffu, lo, src);
                float t1 = __shfl_sync(0xffffffffu, hi, src);
                float u0 = __shfl_sync(0xffffffffu, lo, src + 16);
                float u1 = __shfl_sync(0xffffffffu, hi, src + 16);
                bt[ni][0] = og ? t1 : t0;
                bt[ni][1] = og ? u1 : u0;
            }
            float4 v0 = *(const float4*)&Vs[kc3 * 512 + lane * 4];
            float4 v1 = *(const float4*)&Vs[kc3 * 512 + 128 + lane * 4];
            float4 v2 = *(const float4*)&Vs[kc3 * 512 + 256 + lane * 4];
            float4 v3 = *(const float4*)&Vs[kc3 * 512 + 384 + lane * 4];
#pragma unroll
            for (int ni = 0; ni < 2; ni++) {
                mma8(Oacc[0][ni], &v0.x, bt[ni]);
                mma8(Oacc[1][ni], &v1.x, bt[ni]);
                mma8(Oacc[2][ni], &v2.x, bt[ni]);
                mma8(Oacc[3][ni], &v3.x, bt[ni]);
            }
        }
    }
    CP_WAIT(0);
    __syncthreads();

    // ---- epilogue: stage O as [n][vh] (tf32) ----
    float* Os = sm;   // [32][OSS]
#pragma unroll
    for (int vi = 0; vi < 4; vi++)
#pragma unroll
        for (int ni = 0; ni < 2; ni++) {
            int nl = wgrp * 2 + ni;
            int v = vi * 16 + gid;
            *(float2*)&Os[nl * OSS + v * 8 + tig * 2] =
                make_float2(to_tf32(Oacc[vi][ni][0]), to_tf32(Oacc[vi][ni][1]));
            *(float2*)&Os[nl * OSS + (v + 8) * 8 + tig * 2] =
                make_float2(to_tf32(Oacc[vi][ni][2]), to_tf32(Oacc[vi][ni][3]));
        }
    __syncthreads();

    // ---- res = Wo @ O via mma, Wo A-fragments from gmem (L2) ----
    float racc[4][4] = {};
    const float* WoP = g_WoP + wgrp * 8192;
#pragma unroll 4
    for (int vh0c = 0; vh0c < 16; vh0c++) {
#pragma unroll
        for (int kc = 0; kc < 4; kc++) {
            float4 a = *(const float4*)&WoP[(vh0c * 4 + kc) * 128 + lane * 4];
            int k0 = vh0c * 32 + kc * 8;
#pragma unroll
            for (int ni = 0; ni < 4; ni++) {
                float bf[2];
                bf[0] = Os[(ni * 8 + gid) * OSS + k0 + tig];
                bf[1] = Os[(ni * 8 + gid) * OSS + k0 + tig + 4];
                mma8(racc[ni], &a.x, bf);
            }
        }
    }

    float* ob = out + b * (D * NN);
    const int d = wgrp * 16 + gid;
#pragma unroll
    for (int ni = 0; ni < 4; ni++) {
        *(float2*)&ob[d * NN + n0 + ni * 8 + tig * 2] =
            make_float2(racc[ni][0], racc[ni][1]);
        *(float2*)&ob[(d + 8) * NN + n0 + ni * 8 + tig * 2] =
            make_float2(racc[ni][2], racc[ni][3]);
    }
}

// ---------------- launcher ----------------
extern "C" void kernel_launch(void* const* d_in, const int* in_sizes, int n_in,
                              void* d_out, int out_size) {
    const float* x     = (const float*)d_in[0];
    const float* value = (const float*)d_in[1];
    const float* Wq    = (const float*)d_in[2];
    const float* Wk    = (const float*)d_in[3];
    const float* Wv    = (const float*)d_in[4];
    const float* Wo    = (const float*)d_in[5];
    float* out = (float*)d_out;

    pack_weights<<<512, 256>>>(Wq, Wk, Wv, Wo);
    proj_kv<<<dim3(MM / 128, 1, B), 256>>>(value);

    cudaFuncSetAttribute(mqa_main, cudaFuncAttributeMaxDynamicSharedMemorySize, SMEM_BYTES);
    mqa_main<<<dim3(NN / 32, B), 512, SMEM_BYTES>>>(x, out);
}

// round 8
// speedup vs baseline: 1.0229x; 1.0229x over previous
#include <cuda_runtime.h>
#include <math.h>
#include <stdint.h>

#define B 8
#define D 256
#define NN 1024
#define MM 1024
#define H 8
#define KD 64
#define VD 64
#define KVR 128

// smem (floats): 4 stages x (K 2048 | V 2048) = 16384 | Xs/Qsm @16384
#define XS_OFF 16384
#define XSP 40              // Xs [256][40]
#define QSM_OFF 16384
#define QSP 264             // Qsm [64][264]  (k rows, nh cols)
#define SMEM_FLOATS (QSM_OFF + 64 * QSP)   // 33280
#define SMEM_BYTES (SMEM_FLOATS * 4)
#define OSS 524             // epilogue Os [32][OSS] @ sm+0

#define QSCALE 0.1803368801f   // 0.125 * log2(e)

__device__ float g_WkvT[KVR * D];
__device__ float g_WqP[512 * D];         // Wq A-frag packed (8-warp), pre-scaled tf32
__device__ float g_K[B * 32 * 8 * 256];  // K fragment-packed per 32-m chunk
__device__ float g_V[B * 32 * 4 * 512];  // V fragment-packed per 32-m chunk
__device__ float g_WoP[D * 512];         // Wo A-frag packed (8-warp), tf32

__device__ __forceinline__ float to_tf32(float x) {
    uint32_t u;
    asm("cvt.rna.tf32.f32 %0, %1;" : "=r"(u) : "f"(x));
    return __uint_as_float(u);
}
__device__ __forceinline__ float ex2(float x) {
    float r; asm("ex2.approx.f32 %0, %1;" : "=f"(r) : "f"(x)); return r;
}
__device__ __forceinline__ float rcp(float x) {
    float r; asm("rcp.approx.f32 %0, %1;" : "=f"(r) : "f"(x)); return r;
}
__device__ __forceinline__ void mma8(float* c, const float* a, const float* b) {
    asm volatile(
        "mma.sync.aligned.m16n8k8.row.col.f32.tf32.tf32.f32 "
        "{%0,%1,%2,%3}, {%4,%5,%6,%7}, {%8,%9}, {%0,%1,%2,%3};\n"
        : "+f"(c[0]), "+f"(c[1]), "+f"(c[2]), "+f"(c[3])
        : "r"(__float_as_uint(a[0])), "r"(__float_as_uint(a[1])),
          "r"(__float_as_uint(a[2])), "r"(__float_as_uint(a[3])),
          "r"(__float_as_uint(b[0])), "r"(__float_as_uint(b[1])));
}
__device__ __forceinline__ void cp16(uint32_t dst, const float* src) {
    asm volatile("cp.async.cg.shared.global [%0], [%1], 16;\n"
                 :: "r"(dst), "l"(src));
}
#define CP_COMMIT() asm volatile("cp.async.commit_group;\n" ::)
#define CP_WAIT(n)  asm volatile("cp.async.wait_group %0;\n" :: "n"(n))

// ---------------- kernel 0: pack weights ----------------
__global__ void pack_weights(const float* __restrict__ Wq,
                             const float* __restrict__ Wk,
                             const float* __restrict__ Wv,
                             const float* __restrict__ Wo) {
    int i = blockIdx.x * blockDim.x + threadIdx.x;
    if (i < KVR * D) {
        int r = i / D, d = i % D;
        g_WkvT[i] = (r < 64) ? Wk[d * KD + r] : Wv[d * VD + (r - 64)];
    }
    if (i < 512 * D) {   // WqP: [w8][kc32][mi4][lane32][e4]
        int e = i & 3, ln = (i >> 2) & 31, mi = (i >> 7) & 3;
        int kc = (i >> 9) & 31, w = (i >> 14) & 7;
        int gid = ln >> 2, tig = ln & 3;
        int rk = w * 64 + mi * 16 + gid + 8 * (e & 1);
        int d = kc * 8 + tig + 4 * (e >> 1);
        int kq = rk >> 3, h = rk & 7;
        g_WqP[i] = to_tf32(Wq[h * (D * KD) + d * KD + kq] * QSCALE);
    }
    if (i < D * 512) {   // WoP: [w8][vh0c16][kc4][mi2][lane32][f4]
        int f = i & 3, ln = (i >> 2) & 31, mi = (i >> 7) & 1;
        int kc = (i >> 8) & 3, vh0c = (i >> 10) & 15, w = (i >> 14) & 7;
        int gid = ln >> 2, tig = ln & 3;
        int d = w * 32 + mi * 16 + gid + 8 * (f & 1);
        int vh = vh0c * 32 + kc * 8 + tig + 4 * (f >> 1);
        g_WoP[i] = to_tf32(Wo[d * 512 + vh]);
    }
}

// ---------------- kernel 1: K/V projection GEMM ----------------
__global__ void __launch_bounds__(256) proj_kv(const float* __restrict__ X) {
    const int b = blockIdx.z, n0 = blockIdx.x * 128;
    const float* A = g_WkvT;
    const float* Xb = X + b * (D * NN);

    __shared__ float As[16 * 136];
    __shared__ float Xs[16 * 128];

    float acc[8][8] = {};
    const int tid = threadIdx.x;
    const int tr = tid >> 4, tn = tid & 15;

    for (int dc = 0; dc < D; dc += 16) {
#pragma unroll
        for (int i = 0; i < 8; i++) {
            int idx = tid + i * 256;
            int rr = idx >> 4, c = idx & 15;
            As[c * 136 + rr] = A[rr * D + dc + c];
        }
#pragma unroll
        for (int i = 0; i < 8; i++) {
            int idx = tid + i * 256;
            int c = idx >> 7, nn = idx & 127;
            Xs[c * 128 + nn] = Xb[(dc + c) * NN + n0 + nn];
        }
        __syncthreads();
#pragma unroll
        for (int c = 0; c < 16; c++) {
            float4 a0 = *(const float4*)&As[c * 136 + tr * 4];
            float4 a1 = *(const float4*)&As[c * 136 + 64 + tr * 4];
            float4 x0 = *(const float4*)&Xs[c * 128 + tn * 4];
            float4 x1 = *(const float4*)&Xs[c * 128 + 64 + tn * 4];
            float ra[8] = {a0.x, a0.y, a0.z, a0.w, a1.x, a1.y, a1.z, a1.w};
            float rx[8] = {x0.x, x0.y, x0.z, x0.w, x1.x, x1.y, x1.z, x1.w};
#pragma unroll
            for (int i = 0; i < 8; i++)
#pragma unroll
                for (int j = 0; j < 8; j++) acc[i][j] += ra[i] * rx[j];
        }
        __syncthreads();
    }

#pragma unroll
    for (int i = 0; i < 8; i++) {
        int r = tr * 4 + (i & 3) + (i >> 2) * 64;
#pragma unroll
        for (int j = 0; j < 8; j++) {
            int n = n0 + tn * 4 + (j & 3) + (j >> 2) * 64;
            float v = to_tf32(acc[i][j]);
            if (r < 64) {
                int k = r, m = n;
                int addr = (((b * 32 + (m >> 5)) * 8 + (k >> 3)) << 8)
                         + (((m >> 4) & 1) << 7)
                         + (((m & 7) * 4 + (k & 3)) << 2)
                         + (((k >> 2) & 1) << 1) + ((m >> 3) & 1);
                g_K[addr] = v;
            } else {
                int vv = r - 64, m = n, mc = m & 31;
                int addr = (((b * 32 + (m >> 5)) * 4 + (mc >> 3)) << 9)
                         + ((vv >> 4) << 7)
                         + (((vv & 7) * 4 + (mc & 3)) << 2)
                         + (((mc >> 2) & 1) << 1) + ((vv >> 3) & 1);
                g_V[addr] = v;
            }
        }
    }
}

// ---------------- kernel 2: fused main (256 thr, 8 warps, 32 cols/warp) ----------------
__global__ void __launch_bounds__(256, 1) mqa_main(const float* __restrict__ x,
                                                   float* __restrict__ out) {
    extern __shared__ float sm[];

    const int b = blockIdx.y;
    const int n0 = blockIdx.x * 32;
    const int tid = threadIdx.x;
    const int lane = tid & 31;
    const int wgrp = tid >> 5;   // 0..7
    const int gid = lane >> 2;
    const int tig = lane & 3;

    const float* Kg = g_K + b * 65536;
    const float* Vg = g_V + b * 65536;

    // issue first 3 K/V stages via cp.async (stage = 4096 floats: K 2048 | V 2048)
    const uint32_t smem_u32 = (uint32_t)__cvta_generic_to_shared(sm);
#pragma unroll
    for (int s = 0; s < 3; s++) {
        uint32_t dk = smem_u32 + s * 16384 + tid * 16;
        cp16(dk,         Kg + s * 2048 + tid * 4);
        cp16(dk + 4096,  Kg + s * 2048 + 1024 + tid * 4);
        cp16(dk + 8192,  Vg + s * 2048 + tid * 4);
        cp16(dk + 12288, Vg + s * 2048 + 1024 + tid * 4);
        CP_COMMIT();
    }

    // ---- prologue: Q projection via MMA ----
    float Qreg[8][4][2];
    {
        float* Xs = sm + XS_OFF;   // [256][40]
        const float* Xb = x + b * (D * NN);
#pragma unroll
        for (int i = 0; i < 32; i++) {
            int idx = tid + i * 256;
            int d = idx >> 5, n = idx & 31;
            Xs[d * XSP + n] = to_tf32(Xb[d * NN + n0 + n]);
        }
        __syncthreads();

        float qa[4][4][4] = {};
        const float* WqPw = g_WqP + wgrp * 16384;
#pragma unroll 4
        for (int kc = 0; kc < 32; kc++) {
            float bf[4][2];
#pragma unroll
            for (int ni = 0; ni < 4; ni++) {
                bf[ni][0] = Xs[(kc * 8 + tig) * XSP + ni * 8 + gid];
                bf[ni][1] = Xs[(kc * 8 + tig + 4) * XSP + ni * 8 + gid];
            }
#pragma unroll
            for (int mi = 0; mi < 4; mi++) {
                float4 a = *(const float4*)&WqPw[(kc * 4 + mi) * 128 + lane * 4];
#pragma unroll
                for (int ni = 0; ni < 4; ni++) mma8(qa[mi][ni], &a.x, bf[ni]);
            }
        }
        __syncthreads();   // Xs reads done before Qsm overwrites

        // store Q [64k][256nh]: rk=(k*8+h) row, n col -> Qsm[k][n*8+h]
        float* Qsm = sm + QSM_OFF;   // [64][264]
#pragma unroll
        for (int mi = 0; mi < 4; mi++)
#pragma unroll
            for (int ni = 0; ni < 4; ni++)
#pragma unroll
                for (int r = 0; r < 4; r++) {
                    int rk = wgrp * 64 + mi * 16 + gid + 8 * (r >> 1);
                    int n = ni * 8 + tig * 2 + (r & 1);
                    Qsm[(rk >> 3) * QSP + n * 8 + (rk & 7)] = to_tf32(qa[mi][ni][r]);
                }
        __syncthreads();

        // persistent Q B-frags: col = wgrp*32 + ni*8 + gid, k = kc*8 + tig + 4e
#pragma unroll
        for (int kc = 0; kc < 8; kc++)
#pragma unroll
            for (int ni = 0; ni < 4; ni++)
#pragma unroll
                for (int e = 0; e < 2; e++)
                    Qreg[kc][ni][e] =
                        Qsm[(kc * 8 + tig + 4 * e) * QSP + wgrp * 32 + ni * 8 + gid];
    }

    float Oacc[4][4][4] = {};
    const int src = tig * 4 + (gid >> 1);
    const bool og = gid & 1;

    for (int mch = 0; mch < 32; mch++) {
        CP_WAIT(2);
        __syncthreads();

        if (mch + 3 < 32) {
            int s = (mch + 3) & 3;
            uint32_t dk = smem_u32 + s * 16384 + tid * 16;
            cp16(dk,         Kg + (mch + 3) * 2048 + tid * 4);
            cp16(dk + 4096,  Kg + (mch + 3) * 2048 + 1024 + tid * 4);
            cp16(dk + 8192,  Vg + (mch + 3) * 2048 + tid * 4);
            cp16(dk + 12288, Vg + (mch + 3) * 2048 + 1024 + tid * 4);
        }
        CP_COMMIT();

        const float* Ks = sm + (mch & 3) * 4096;
        const float* Vs = Ks + 2048;

        // ---- phase 1: logits (Q from registers) ----
        float c1[2][4][4] = {};
#pragma unroll
        for (int kc = 0; kc < 8; kc++) {
            float4 a0 = *(const float4*)&Ks[kc * 256 + lane * 4];
            float4 a1 = *(const float4*)&Ks[kc * 256 + 128 + lane * 4];
#pragma unroll
            for (int ni = 0; ni < 4; ni++) {
                mma8(c1[0][ni], &a0.x, Qreg[kc][ni]);
                mma8(c1[1][ni], &a1.x, Qreg[kc][ni]);
            }
        }

        // ---- softmax over heads ----
#pragma unroll
        for (int mi = 0; mi < 2; mi++)
#pragma unroll
            for (int ni = 0; ni < 4; ni++) {
                float* cc = c1[mi][ni];
                float e0 = ex2(cc[0]), e1 = ex2(cc[1]);
                float sa = e0 + e1;
                sa += __shfl_xor_sync(0xffffffffu, sa, 1);
                sa += __shfl_xor_sync(0xffffffffu, sa, 2);
                float ra = rcp(sa);
                cc[0] = to_tf32(e0 * ra); cc[1] = to_tf32(e1 * ra);
                float e2 = ex2(cc[2]), e3 = ex2(cc[3]);
                float sb = e2 + e3;
                sb += __shfl_xor_sync(0xffffffffu, sb, 1);
                sb += __shfl_xor_sync(0xffffffffu, sb, 2);
                float rb = rcp(sb);
                cc[2] = to_tf32(e2 * rb); cc[3] = to_tf32(e3 * rb);
            }

        // ---- phase 3: transpose (per kc3) + O += V @ attn ----
#pragma unroll
        for (int kc3 = 0; kc3 < 4; kc3++) {
            const int mi = kc3 >> 1, p = kc3 & 1;
            float bt[4][2];
#pragma unroll
            for (int ni = 0; ni < 4; ni++) {
                float lo = c1[mi][ni][2 * p], hi = c1[mi][ni][2 * p + 1];
                float t0 = __shfl_sync(0xffffffffu, lo, src);
                float t1 = __shfl_sync(0xffffffffu, hi, src);
                float u0 = __shfl_sync(0xffffffffu, lo, src + 16);
                float u1 = __shfl_sync(0xffffffffu, hi, src + 16);
                bt[ni][0] = og ? t1 : t0;
                bt[ni][1] = og ? u1 : u0;
            }
            float4 v0 = *(const float4*)&Vs[kc3 * 512 + lane * 4];
            float4 v1 = *(const float4*)&Vs[kc3 * 512 + 128 + lane * 4];
            float4 v2 = *(const float4*)&Vs[kc3 * 512 + 256 + lane * 4];
            float4 v3 = *(const float4*)&Vs[kc3 * 512 + 384 + lane * 4];
#pragma unroll
            for (int ni = 0; ni < 4; ni++) {
                mma8(Oacc[0][ni], &v0.x, bt[ni]);
                mma8(Oacc[1][ni], &v1.x, bt[ni]);
                mma8(Oacc[2][ni], &v2.x, bt[ni]);
                mma8(Oacc[3][ni], &v3.x, bt[ni]);
            }
        }
    }
    CP_WAIT(0);
    __syncthreads();

    // ---- epilogue: stage O as [n][vh] (tf32) ----
    float* Os = sm;   // [32][OSS]
#pragma unroll
    for (int vi = 0; vi < 4; vi++)
#pragma unroll
        for (int ni = 0; ni < 4; ni++) {
            int nl = wgrp * 4 + ni;
            int v = vi * 16 + gid;
            *(float2*)&Os[nl * OSS + v * 8 + tig * 2] =
                make_float2(to_tf32(Oacc[vi][ni][0]), to_tf32(Oacc[vi][ni][1]));
            *(float2*)&Os[nl * OSS + (v + 8) * 8 + tig * 2] =
                make_float2(to_tf32(Oacc[vi][ni][2]), to_tf32(Oacc[vi][ni][3]));
        }
    __syncthreads();

    // ---- res = Wo @ O via mma, Wo A-fragments from gmem (L2) ----
    float racc[2][4][4] = {};
    const float* WoP = g_WoP + wgrp * 16384;
#pragma unroll 2
    for (int vh0c = 0; vh0c < 16; vh0c++) {
#pragma unroll
        for (int kc = 0; kc < 4; kc++) {
            float4 a0 = *(const float4*)&WoP[(vh0c * 8 + kc * 2) * 128 + lane * 4];
            float4 a1 = *(const float4*)&WoP[(vh0c * 8 + kc * 2 + 1) * 128 + lane * 4];
            int k0 = vh0c * 32 + kc * 8;
#pragma unroll
            for (int ni = 0; ni < 4; ni++) {
                float bf[2];
                bf[0] = Os[(ni * 8 + gid) * OSS + k0 + tig];
                bf[1] = Os[(ni * 8 + gid) * OSS + k0 + tig + 4];
                mma8(racc[0][ni], &a0.x, bf);
                mma8(racc[1][ni], &a1.x, bf);
            }
        }
    }

    float* ob = out + b * (D * NN);
#pragma unroll
    for (int mi = 0; mi < 2; mi++)
#pragma unroll
        for (int ni = 0; ni < 4; ni++) {
            int d = wgrp * 32 + mi * 16 + gid;
            *(float2*)&ob[d * NN + n0 + ni * 8 + tig * 2] =
                make_float2(racc[mi][ni][0], racc[mi][ni][1]);
            *(float2*)&ob[(d + 8) * NN + n0 + ni * 8 + tig * 2] =
                make_float2(racc[mi][ni][2], racc[mi][ni][3]);
        }
}

// ---------------- launcher ----------------
extern "C" void kernel_launch(void* const* d_in, const int* in_sizes, int n_in,
                              void* d_out, int out_size) {
    const float* x     = (const float*)d_in[0];
    const float* value = (const float*)d_in[1];
    const float* Wq    = (const float*)d_in[2];
    const float* Wk    = (const float*)d_in[3];
    const float* Wv    = (const float*)d_in[4];
    const float* Wo    = (const float*)d_in[5];
    float* out = (float*)d_out;

    pack_weights<<<512, 256>>>(Wq, Wk, Wv, Wo);
    proj_kv<<<dim3(MM / 128, 1, B), 256>>>(value);

    cudaFuncSetAttribute(mqa_main, cudaFuncAttributeMaxDynamicSharedMemorySize, SMEM_BYTES);
    mqa_main<<<dim3(NN / 32, B), 256, SMEM_BYTES>>>(x, out);
}

// round 9
// speedup vs baseline: 1.0290x; 1.0059x over previous
#include <cuda_runtime.h>
#include <math.h>
#include <stdint.h>

#define B 8
#define D 256
#define NN 1024
#define MM 1024
#define H 8
#define KD 64
#define VD 64
#define KVR 128

// smem (floats): 5 stages x (K 2048 | V 2048) = 20480 | Xs/Qsm overlay @20480
#define NSTAGE 5
#define XS_OFF 20480
#define XSP 40              // Xs [256][40]
#define QSM_OFF 20480
#define QSP 264             // Qsm [64][264]
#define SMEM_FLOATS (QSM_OFF + 64 * QSP)   // 37376
#define SMEM_BYTES (SMEM_FLOATS * 4)
#define OSS 524             // epilogue Os [32][OSS] @ sm+0

#define QSCALE 0.1803368801f   // 0.125 * log2(e)

__device__ float g_WkvT[KVR * D];
__device__ float g_WqP[512 * D];         // Wq A-frag packed (8-warp), pre-scaled tf32
__device__ float g_K[B * 32 * 8 * 256];  // K fragment-packed per 32-m chunk
__device__ float g_V[B * 32 * 4 * 512];  // V fragment-packed per 32-m chunk
__device__ float g_WoP[D * 512];         // Wo A-frag packed (8-warp), tf32

__device__ __forceinline__ float to_tf32(float x) {
    uint32_t u;
    asm("cvt.rna.tf32.f32 %0, %1;" : "=r"(u) : "f"(x));
    return __uint_as_float(u);
}
__device__ __forceinline__ float ex2(float x) {
    float r; asm("ex2.approx.f32 %0, %1;" : "=f"(r) : "f"(x)); return r;
}
__device__ __forceinline__ float rcp(float x) {
    float r; asm("rcp.approx.f32 %0, %1;" : "=f"(r) : "f"(x)); return r;
}
__device__ __forceinline__ void mma8(float* c, const float* a, const float* b) {
    asm volatile(
        "mma.sync.aligned.m16n8k8.row.col.f32.tf32.tf32.f32 "
        "{%0,%1,%2,%3}, {%4,%5,%6,%7}, {%8,%9}, {%0,%1,%2,%3};\n"
        : "+f"(c[0]), "+f"(c[1]), "+f"(c[2]), "+f"(c[3])
        : "r"(__float_as_uint(a[0])), "r"(__float_as_uint(a[1])),
          "r"(__float_as_uint(a[2])), "r"(__float_as_uint(a[3])),
          "r"(__float_as_uint(b[0])), "r"(__float_as_uint(b[1])));
}
// zero-accumulator form: C_in = 0 (kills per-iter zeroing movs)
__device__ __forceinline__ void mma8z(float* c, const float* a, const float* b) {
    asm volatile(
        "mma.sync.aligned.m16n8k8.row.col.f32.tf32.tf32.f32 "
        "{%0,%1,%2,%3}, {%4,%5,%6,%7}, {%8,%9}, {%10,%10,%10,%10};\n"
        : "=f"(c[0]), "=f"(c[1]), "=f"(c[2]), "=f"(c[3])
        : "r"(__float_as_uint(a[0])), "r"(__float_as_uint(a[1])),
          "r"(__float_as_uint(a[2])), "r"(__float_as_uint(a[3])),
          "r"(__float_as_uint(b[0])), "r"(__float_as_uint(b[1])),
          "f"(0.0f));
}
__device__ __forceinline__ void cp16(uint32_t dst, const float* src) {
    asm volatile("cp.async.cg.shared.global [%0], [%1], 16;\n"
                 :: "r"(dst), "l"(src));
}
#define CP_COMMIT() asm volatile("cp.async.commit_group;\n" ::)
#define CP_WAIT(n)  asm volatile("cp.async.wait_group %0;\n" :: "n"(n))

// ---------------- kernel 0: pack weights ----------------
__global__ void pack_weights(const float* __restrict__ Wq,
                             const float* __restrict__ Wk,
                             const float* __restrict__ Wv,
                             const float* __restrict__ Wo) {
    int i = blockIdx.x * blockDim.x + threadIdx.x;
    if (i < KVR * D) {
        int r = i / D, d = i % D;
        g_WkvT[i] = (r < 64) ? Wk[d * KD + r] : Wv[d * VD + (r - 64)];
    }
    if (i < 512 * D) {   // WqP: [w8][kc32][mi4][lane32][e4]
        int e = i & 3, ln = (i >> 2) & 31, mi = (i >> 7) & 3;
        int kc = (i >> 9) & 31, w = (i >> 14) & 7;
        int gid = ln >> 2, tig = ln & 3;
        int rk = w * 64 + mi * 16 + gid + 8 * (e & 1);
        int d = kc * 8 + tig + 4 * (e >> 1);
        int kq = rk >> 3, h = rk & 7;
        g_WqP[i] = to_tf32(Wq[h * (D * KD) + d * KD + kq] * QSCALE);
    }
    if (i < D * 512) {   // WoP: [w8][vh0c16][kc4][mi2][lane32][f4]
        int f = i & 3, ln = (i >> 2) & 31, mi = (i >> 7) & 1;
        int kc = (i >> 8) & 3, vh0c = (i >> 10) & 15, w = (i >> 14) & 7;
        int gid = ln >> 2, tig = ln & 3;
        int d = w * 32 + mi * 16 + gid + 8 * (f & 1);
        int vh = vh0c * 32 + kc * 8 + tig + 4 * (f >> 1);
        g_WoP[i] = to_tf32(Wo[d * 512 + vh]);
    }
}

// ---------------- kernel 1: K/V projection GEMM ----------------
__global__ void __launch_bounds__(256) proj_kv(const float* __restrict__ X) {
    const int b = blockIdx.z, n0 = blockIdx.x * 128;
    const float* A = g_WkvT;
    const float* Xb = X + b * (D * NN);

    __shared__ float As[16 * 136];
    __shared__ float Xs[16 * 128];

    float acc[8][8] = {};
    const int tid = threadIdx.x;
    const int tr = tid >> 4, tn = tid & 15;

    for (int dc = 0; dc < D; dc += 16) {
#pragma unroll
        for (int i = 0; i < 8; i++) {
            int idx = tid + i * 256;
            int rr = idx >> 4, c = idx & 15;
            As[c * 136 + rr] = A[rr * D + dc + c];
        }
#pragma unroll
        for (int i = 0; i < 8; i++) {
            int idx = tid + i * 256;
            int c = idx >> 7, nn = idx & 127;
            Xs[c * 128 + nn] = Xb[(dc + c) * NN + n0 + nn];
        }
        __syncthreads();
#pragma unroll
        for (int c = 0; c < 16; c++) {
            float4 a0 = *(const float4*)&As[c * 136 + tr * 4];
            float4 a1 = *(const float4*)&As[c * 136 + 64 + tr * 4];
            float4 x0 = *(const float4*)&Xs[c * 128 + tn * 4];
            float4 x1 = *(const float4*)&Xs[c * 128 + 64 + tn * 4];
            float ra[8] = {a0.x, a0.y, a0.z, a0.w, a1.x, a1.y, a1.z, a1.w};
            float rx[8] = {x0.x, x0.y, x0.z, x0.w, x1.x, x1.y, x1.z, x1.w};
#pragma unroll
            for (int i = 0; i < 8; i++)
#pragma unroll
                for (int j = 0; j < 8; j++) acc[i][j] += ra[i] * rx[j];
        }
        __syncthreads();
    }

#pragma unroll
    for (int i = 0; i < 8; i++) {
        int r = tr * 4 + (i & 3) + (i >> 2) * 64;
#pragma unroll
        for (int j = 0; j < 8; j++) {
            int n = n0 + tn * 4 + (j & 3) + (j >> 2) * 64;
            float v = to_tf32(acc[i][j]);
            if (r < 64) {
                int k = r, m = n;
                int addr = (((b * 32 + (m >> 5)) * 8 + (k >> 3)) << 8)
                         + (((m >> 4) & 1) << 7)
                         + (((m & 7) * 4 + (k & 3)) << 2)
                         + (((k >> 2) & 1) << 1) + ((m >> 3) & 1);
                g_K[addr] = v;
            } else {
                int vv = r - 64, m = n, mc = m & 31;
                int addr = (((b * 32 + (m >> 5)) * 4 + (mc >> 3)) << 9)
                         + ((vv >> 4) << 7)
                         + (((vv & 7) * 4 + (mc & 3)) << 2)
                         + (((mc >> 2) & 1) << 1) + ((vv >> 3) & 1);
                g_V[addr] = v;
            }
        }
    }
}

// ---------------- kernel 2: fused main (256 thr, cross-chunk pipelined) ----------------
__global__ void __launch_bounds__(256, 1) mqa_main(const float* __restrict__ x,
                                                   float* __restrict__ out) {
    extern __shared__ float sm[];

    const int b = blockIdx.y;
    const int n0 = blockIdx.x * 32;
    const int tid = threadIdx.x;
    const int lane = tid & 31;
    const int wgrp = tid >> 5;   // 0..7
    const int gid = lane >> 2;
    const int tig = lane & 3;

    const float* Kg = g_K + b * 65536;
    const float* Vg = g_V + b * 65536;

    const uint32_t smem_u32 = (uint32_t)__cvta_generic_to_shared(sm);
    // issue first 4 K/V stages
#pragma unroll
    for (int s = 0; s < 4; s++) {
        uint32_t dk = smem_u32 + s * 16384 + tid * 16;
        cp16(dk,         Kg + s * 2048 + tid * 4);
        cp16(dk + 4096,  Kg + s * 2048 + 1024 + tid * 4);
        cp16(dk + 8192,  Vg + s * 2048 + tid * 4);
        cp16(dk + 12288, Vg + s * 2048 + 1024 + tid * 4);
        CP_COMMIT();
    }

    // ---- prologue: Q projection via MMA ----
    float Qreg[8][4][2];
    {
        float* Xs = sm + XS_OFF;   // [256][40]
        const float* Xb = x + b * (D * NN);
#pragma unroll
        for (int i = 0; i < 32; i++) {
            int idx = tid + i * 256;
            int d = idx >> 5, n = idx & 31;
            Xs[d * XSP + n] = to_tf32(Xb[d * NN + n0 + n]);
        }
        __syncthreads();

        float qa[4][4][4] = {};
        const float* WqPw = g_WqP + wgrp * 16384;
#pragma unroll 4
        for (int kc = 0; kc < 32; kc++) {
            float bf[4][2];
#pragma unroll
            for (int ni = 0; ni < 4; ni++) {
                bf[ni][0] = Xs[(kc * 8 + tig) * XSP + ni * 8 + gid];
                bf[ni][1] = Xs[(kc * 8 + tig + 4) * XSP + ni * 8 + gid];
            }
#pragma unroll
            for (int mi = 0; mi < 4; mi++) {
                float4 a = *(const float4*)&WqPw[(kc * 4 + mi) * 128 + lane * 4];
#pragma unroll
                for (int ni = 0; ni < 4; ni++) mma8(qa[mi][ni], &a.x, bf[ni]);
            }
        }
        __syncthreads();   // Xs reads done before Qsm overwrites

        float* Qsm = sm + QSM_OFF;   // [64][264]
#pragma unroll
        for (int mi = 0; mi < 4; mi++)
#pragma unroll
            for (int ni = 0; ni < 4; ni++)
#pragma unroll
                for (int r = 0; r < 4; r++) {
                    int rk = wgrp * 64 + mi * 16 + gid + 8 * (r >> 1);
                    int n = ni * 8 + tig * 2 + (r & 1);
                    Qsm[(rk >> 3) * QSP + n * 8 + (rk & 7)] = to_tf32(qa[mi][ni][r]);
                }
        __syncthreads();

#pragma unroll
        for (int kc = 0; kc < 8; kc++)
#pragma unroll
            for (int ni = 0; ni < 4; ni++)
#pragma unroll
                for (int e = 0; e < 2; e++)
                    Qreg[kc][ni][e] =
                        Qsm[(kc * 8 + tig + 4 * e) * QSP + wgrp * 32 + ni * 8 + gid];
    }

    // ---- stage 0 ready; phase1(0) ----
    CP_WAIT(3);
    __syncthreads();

    float c1[2][4][4];
    {
        const float* Ks = sm;   // buffer 0
#pragma unroll
        for (int kc = 0; kc < 8; kc++) {
            float4 a0 = *(const float4*)&Ks[kc * 256 + lane * 4];
            float4 a1 = *(const float4*)&Ks[kc * 256 + 128 + lane * 4];
#pragma unroll
            for (int ni = 0; ni < 4; ni++) {
                if (kc == 0) {
                    mma8z(c1[0][ni], &a0.x, Qreg[0][ni]);
                    mma8z(c1[1][ni], &a1.x, Qreg[0][ni]);
                } else {
                    mma8(c1[0][ni], &a0.x, Qreg[kc][ni]);
                    mma8(c1[1][ni], &a1.x, Qreg[kc][ni]);
                }
            }
        }
    }

    float Oacc[4][4][4] = {};
    const int src = tig * 4 + (gid >> 1);
    const bool og = gid & 1;
    int sW = 4, sP1 = 1, sP3 = 0;

#pragma unroll 1
    for (int mch = 0; mch < 31; mch++) {
        CP_WAIT(2);
        __syncthreads();

        if (mch + 4 < 32) {
            uint32_t dk = smem_u32 + sW * 16384 + tid * 16;
            const float* Kp = Kg + (mch + 4) * 2048 + tid * 4;
            const float* Vp = Vg + (mch + 4) * 2048 + tid * 4;
            cp16(dk, Kp);          cp16(dk + 4096, Kp + 1024);
            cp16(dk + 8192, Vp);   cp16(dk + 12288, Vp + 1024);
        }
        CP_COMMIT();

        // ---- softmax over heads (chunk mch) ----
#pragma unroll
        for (int mi = 0; mi < 2; mi++)
#pragma unroll
            for (int ni = 0; ni < 4; ni++) {
                float* cc = c1[mi][ni];
                float e0 = ex2(cc[0]), e1 = ex2(cc[1]);
                float sa = e0 + e1;
                sa += __shfl_xor_sync(0xffffffffu, sa, 1);
                sa += __shfl_xor_sync(0xffffffffu, sa, 2);
                float ra = rcp(sa);
                cc[0] = to_tf32(e0 * ra); cc[1] = to_tf32(e1 * ra);
                float e2 = ex2(cc[2]), e3 = ex2(cc[3]);
                float sb = e2 + e3;
                sb += __shfl_xor_sync(0xffffffffu, sb, 1);
                sb += __shfl_xor_sync(0xffffffffu, sb, 2);
                float rb = rcp(sb);
                cc[2] = to_tf32(e2 * rb); cc[3] = to_tf32(e3 * rb);
            }

        // ---- transpose all attn C-frags -> B-frags ----
        float bt[4][4][2];
#pragma unroll
        for (int kc3 = 0; kc3 < 4; kc3++) {
            const int mi = kc3 >> 1, p = kc3 & 1;
#pragma unroll
            for (int ni = 0; ni < 4; ni++) {
                float lo = c1[mi][ni][2 * p], hi = c1[mi][ni][2 * p + 1];
                float t0 = __shfl_sync(0xffffffffu, lo, src);
                float t1 = __shfl_sync(0xffffffffu, hi, src);
                float u0 = __shfl_sync(0xffffffffu, lo, src + 16);
                float u1 = __shfl_sync(0xffffffffu, hi, src + 16);
                bt[kc3][ni][0] = og ? t1 : t0;
                bt[kc3][ni][1] = og ? u1 : u0;
            }
        }

        // ---- phase1 for chunk mch+1 (independent of softmax/transpose above;
        //      overwrites c1, which is fully consumed into bt) ----
        {
            const float* Ks = sm + sP1 * 4096;
#pragma unroll
            for (int kc = 0; kc < 8; kc++) {
                float4 a0 = *(const float4*)&Ks[kc * 256 + lane * 4];
                float4 a1 = *(const float4*)&Ks[kc * 256 + 128 + lane * 4];
#pragma unroll
                for (int ni = 0; ni < 4; ni++) {
                    if (kc == 0) {
                        mma8z(c1[0][ni], &a0.x, Qreg[0][ni]);
                        mma8z(c1[1][ni], &a1.x, Qreg[0][ni]);
                    } else {
                        mma8(c1[0][ni], &a0.x, Qreg[kc][ni]);
                        mma8(c1[1][ni], &a1.x, Qreg[kc][ni]);
                    }
                }
            }
        }

        // ---- phase3: O += V @ attn (chunk mch) ----
        {
            const float* Vs = sm + sP3 * 4096 + 2048;
#pragma unroll
            for (int kc3 = 0; kc3 < 4; kc3++) {
                float4 v0 = *(const float4*)&Vs[kc3 * 512 + lane * 4];
                float4 v1 = *(const float4*)&Vs[kc3 * 512 + 128 + lane * 4];
                float4 v2 = *(const float4*)&Vs[kc3 * 512 + 256 + lane * 4];
                float4 v3 = *(const float4*)&Vs[kc3 * 512 + 384 + lane * 4];
#pragma unroll
                for (int ni = 0; ni < 4; ni++) {
                    mma8(Oacc[0][ni], &v0.x, bt[kc3][ni]);
                    mma8(Oacc[1][ni], &v1.x, bt[kc3][ni]);
                    mma8(Oacc[2][ni], &v2.x, bt[kc3][ni]);
                    mma8(Oacc[3][ni], &v3.x, bt[kc3][ni]);
                }
            }
        }

        sW = (sW == NSTAGE - 1) ? 0 : sW + 1;
        sP1 = (sP1 == NSTAGE - 1) ? 0 : sP1 + 1;
        sP3 = (sP3 == NSTAGE - 1) ? 0 : sP3 + 1;
    }

    // ---- peeled final chunk (mch = 31): softmax + transpose + phase3 ----
    {
#pragma unroll
        for (int mi = 0; mi < 2; mi++)
#pragma unroll
            for (int ni = 0; ni < 4; ni++) {
                float* cc = c1[mi][ni];
                float e0 = ex2(cc[0]), e1 = ex2(cc[1]);
                float sa = e0 + e1;
                sa += __shfl_xor_sync(0xffffffffu, sa, 1);
                sa += __shfl_xor_sync(0xffffffffu, sa, 2);
                float ra = rcp(sa);
                cc[0] = to_tf32(e0 * ra); cc[1] = to_tf32(e1 * ra);
                float e2 = ex2(cc[2]), e3 = ex2(cc[3]);
                float sb = e2 + e3;
                sb += __shfl_xor_sync(0xffffffffu, sb, 1);
                sb += __shfl_xor_sync(0xffffffffu, sb, 2);
                float rb = rcp(sb);
                cc[2] = to_tf32(e2 * rb); cc[3] = to_tf32(e3 * rb);
            }
        const float* Vs = sm + sP3 * 4096 + 2048;
#pragma unroll
        for (int kc3 = 0; kc3 < 4; kc3++) {
            const int mi = kc3 >> 1, p = kc3 & 1;
            float bt[4][2];
#pragma unroll
            for (int ni = 0; ni < 4; ni++) {
                float lo = c1[mi][ni][2 * p], hi = c1[mi][ni][2 * p + 1];
                float t0 = __shfl_sync(0xffffffffu, lo, src);
                float t1 = __shfl_sync(0xffffffffu, hi, src);
                float u0 = __shfl_sync(0xffffffffu, lo, src + 16);
                float u1 = __shfl_sync(0xffffffffu, hi, src + 16);
                bt[ni][0] = og ? t1 : t0;
                bt[ni][1] = og ? u1 : u0;
            }
            float4 v0 = *(const float4*)&Vs[kc3 * 512 + lane * 4];
            float4 v1 = *(const float4*)&Vs[kc3 * 512 + 128 + lane * 4];
            float4 v2 = *(const float4*)&Vs[kc3 * 512 + 256 + lane * 4];
            float4 v3 = *(const float4*)&Vs[kc3 * 512 + 384 + lane * 4];
#pragma unroll
            for (int ni = 0; ni < 4; ni++) {
                mma8(Oacc[0][ni], &v0.x, bt[ni]);
                mma8(Oacc[1][ni], &v1.x, bt[ni]);
                mma8(Oacc[2][ni], &v2.x, bt[ni]);
                mma8(Oacc[3][ni], &v3.x, bt[ni]);
            }
        }
    }
    CP_WAIT(0);
    __syncthreads();

    // ---- epilogue: stage O as [n][vh] (tf32) ----
    float* Os = sm;   // [32][OSS]
#pragma unroll
    for (int vi = 0; vi < 4; vi++)
#pragma unroll
        for (int ni = 0; ni < 4; ni++) {
            int nl = wgrp * 4 + ni;
            int v = vi * 16 + gid;
            *(float2*)&Os[nl * OSS + v * 8 + tig * 2] =
                make_float2(to_tf32(Oacc[vi][ni][0]), to_tf32(Oacc[vi][ni][1]));
            *(float2*)&Os[nl * OSS + (v + 8) * 8 + tig * 2] =
                make_float2(to_tf32(Oacc[vi][ni][2]), to_tf32(Oacc[vi][ni][3]));
        }
    __syncthreads();

    // ---- res = Wo @ O via mma, Wo A-fragments from gmem (L2) ----
    float racc[2][4][4] = {};
    const float* WoP = g_WoP + wgrp * 16384;
#pragma unroll 2
    for (int vh0c = 0; vh0c < 16; vh0c++) {
#pragma unroll
        for (int kc = 0; kc < 4; kc++) {
            float4 a0 = *(const float4*)&WoP[(vh0c * 8 + kc * 2) * 128 + lane * 4];
            float4 a1 = *(const float4*)&WoP[(vh0c * 8 + kc * 2 + 1) * 128 + lane * 4];
            int k0 = vh0c * 32 + kc * 8;
#pragma unroll
            for (int ni = 0; ni < 4; ni++) {
                float bf[2];
                bf[0] = Os[(ni * 8 + gid) * OSS + k0 + tig];
                bf[1] = Os[(ni * 8 + gid) * OSS + k0 + tig + 4];
                mma8(racc[0][ni], &a0.x, bf);
                mma8(racc[1][ni], &a1.x, bf);
            }
        }
    }

    float* ob = out + b * (D * NN);
#pragma unroll
    for (int mi = 0; mi < 2; mi++)
#pragma unroll
        for (int ni = 0; ni < 4; ni++) {
            int d = wgrp * 32 + mi * 16 + gid;
            *(float2*)&ob[d * NN + n0 + ni * 8 + tig * 2] =
                make_float2(racc[mi][ni][0], racc[mi][ni][1]);
            *(float2*)&ob[(d + 8) * NN + n0 + ni * 8 + tig * 2] =
                make_float2(racc[mi][ni][2], racc[mi][ni][3]);
        }
}

// ---------------- launcher ----------------
extern "C" void kernel_launch(void* const* d_in, const int* in_sizes, int n_in,
                              void* d_out, int out_size) {
    const float* x     = (const float*)d_in[0];
    const float* value = (const float*)d_in[1];
    const float* Wq    = (const float*)d_in[2];
    const float* Wk    = (const float*)d_in[3];
    const float* Wv    = (const float*)d_in[4];
    const float* Wo    = (const float*)d_in[5];
    float* out = (float*)d_out;

    pack_weights<<<512, 256>>>(Wq, Wk, Wv, Wo);
    proj_kv<<<dim3(MM / 128, 1, B), 256>>>(value);

    cudaFuncSetAttribute(mqa_main, cudaFuncAttributeMaxDynamicSharedMemorySize, SMEM_BYTES);
    mqa_main<<<dim3(NN / 32, B), 256, SMEM_BYTES>>>(x, out);
}

// round 10
// speedup vs baseline: 1.4464x; 1.4056x over previous
#include <cuda_runtime.h>
#include <cuda_fp16.h>
#include <math.h>
#include <stdint.h>

#define B 8
#define D 256
#define NN 1024
#define MM 1024
#define KD 64
#define VD 64
#define KVR 128

#define NSTAGE 5
// half-element offsets in smem
#define STAGE_H 4096        // one stage = K 2048 halfs + V 2048 halfs
#define XS_OFF 20480        // Xs [32 n][264 d] halfs (prologue)
#define XSP 264
#define QSM_OFF 20480       // Qsm [256 col][72 k] halfs (after Xs dies)
#define QSP2 72
#define OSP 520             // Os [32 n][520 vh] halfs (epilogue, over stages)
#define SMEM_HALFS (QSM_OFF + 256 * QSP2)   // 38912
#define SMEM_BYTES (SMEM_HALFS * 2)          // 77824

#define QSCALE 0.1803368801f   // 0.125 * log2(e)

__device__ float  g_WkvT[KVR * D];
__device__ __half g_WqP[512 * D];    // Wq A-frags fp16, pre-scaled
__device__ __half g_K[B * 32 * 2048];
__device__ __half g_V[B * 32 * 2048];
__device__ __half g_WoP[D * 512];    // Wo A-frags fp16

__device__ __forceinline__ float ex2(float x) {
    float r; asm("ex2.approx.f32 %0, %1;" : "=f"(r) : "f"(x)); return r;
}
__device__ __forceinline__ float rcp(float x) {
    float r; asm("rcp.approx.f32 %0, %1;" : "=f"(r) : "f"(x)); return r;
}
__device__ __forceinline__ uint32_t prmtb(uint32_t a, uint32_t b, uint32_t s) {
    uint32_t d; asm("prmt.b32 %0, %1, %2, %3;" : "=r"(d) : "r"(a), "r"(b), "r"(s));
    return d;
}
__device__ __forceinline__ uint32_t packh2(float a, float b) {
    __half2 h = __floats2half2_rn(a, b);
    return *reinterpret_cast<uint32_t*>(&h);
}
__device__ __forceinline__ void mmaf16(float* c, const uint32_t* a, const uint32_t* b) {
    asm volatile(
        "mma.sync.aligned.m16n8k16.row.col.f32.f16.f16.f32 "
        "{%0,%1,%2,%3}, {%4,%5,%6,%7}, {%8,%9}, {%0,%1,%2,%3};\n"
        : "+f"(c[0]), "+f"(c[1]), "+f"(c[2]), "+f"(c[3])
        : "r"(a[0]), "r"(a[1]), "r"(a[2]), "r"(a[3]), "r"(b[0]), "r"(b[1]));
}
__device__ __forceinline__ void mmaf16z(float* c, const uint32_t* a, const uint32_t* b) {
    asm volatile(
        "mma.sync.aligned.m16n8k16.row.col.f32.f16.f16.f32 "
        "{%0,%1,%2,%3}, {%4,%5,%6,%7}, {%8,%9}, {%10,%10,%10,%10};\n"
        : "=f"(c[0]), "=f"(c[1]), "=f"(c[2]), "=f"(c[3])
        : "r"(a[0]), "r"(a[1]), "r"(a[2]), "r"(a[3]), "r"(b[0]), "r"(b[1]),
          "f"(0.0f));
}
__device__ __forceinline__ void cp16(uint32_t dst, const void* src) {
    asm volatile("cp.async.cg.shared.global [%0], [%1], 16;\n"
                 :: "r"(dst), "l"(src));
}
#define CP_COMMIT() asm volatile("cp.async.commit_group;\n" ::)
#define CP_WAIT(n)  asm volatile("cp.async.wait_group %0;\n" :: "n"(n))

// ---------------- kernel 0: pack weights ----------------
__global__ void pack_weights(const float* __restrict__ Wq,
                             const float* __restrict__ Wk,
                             const float* __restrict__ Wv,
                             const float* __restrict__ Wo) {
    int i = blockIdx.x * blockDim.x + threadIdx.x;   // up to 131072
    if (i < KVR * D) {
        int r = i / D, d = i % D;
        g_WkvT[i] = (r < 64) ? Wk[d * KD + r] : Wv[d * VD + (r - 64)];
    }
    if (i < 512 * D) {   // WqP: [w8][kc16][mi4][lane32][r4][dlt2]
        int dlt = i & 1, r = (i >> 1) & 3, ln = (i >> 3) & 31;
        int mi = (i >> 8) & 3, kc = (i >> 10) & 15, w = (i >> 14) & 7;
        int g = ln >> 2, t = ln & 3;
        int rk = w * 64 + mi * 16 + g + 8 * (r & 1);
        int d = kc * 16 + 2 * t + dlt + 8 * (r >> 1);
        int kq = rk >> 3, h = rk & 7;
        g_WqP[i] = __float2half_rn(Wq[h * (D * KD) + d * KD + kq] * QSCALE);
    }
    if (i < D * 512) {   // WoP: [w8][ks32][mi2][lane32][r4][dlt2]
        int dlt = i & 1, r = (i >> 1) & 3, ln = (i >> 3) & 31;
        int mi = (i >> 8) & 1, ks = (i >> 9) & 31, w = (i >> 14) & 7;
        int g = ln >> 2, t = ln & 3;
        int d = w * 32 + mi * 16 + g + 8 * (r & 1);
        int vh = ks * 16 + 2 * t + dlt + 8 * (r >> 1);
        g_WoP[i] = __float2half_rn(Wo[d * 512 + vh]);
    }
}

// ---------------- kernel 1: K/V projection GEMM (fp16 fragment output) ----------------
__global__ void __launch_bounds__(256) proj_kv(const float* __restrict__ X) {
    const int b = blockIdx.z, n0 = blockIdx.x * 128;
    const float* A = g_WkvT;
    const float* Xb = X + b * (D * NN);

    __shared__ float As[16 * 136];
    __shared__ float Xs[16 * 128];

    float acc[8][8] = {};
    const int tid = threadIdx.x;
    const int tr = tid >> 4, tn = tid & 15;

    for (int dc = 0; dc < D; dc += 16) {
#pragma unroll
        for (int i = 0; i < 8; i++) {
            int idx = tid + i * 256;
            int rr = idx >> 4, c = idx & 15;
            As[c * 136 + rr] = A[rr * D + dc + c];
        }
#pragma unroll
        for (int i = 0; i < 8; i++) {
            int idx = tid + i * 256;
            int c = idx >> 7, nn = idx & 127;
            Xs[c * 128 + nn] = Xb[(dc + c) * NN + n0 + nn];
        }
        __syncthreads();
#pragma unroll
        for (int c = 0; c < 16; c++) {
            float4 a0 = *(const float4*)&As[c * 136 + tr * 4];
            float4 a1 = *(const float4*)&As[c * 136 + 64 + tr * 4];
            float4 x0 = *(const float4*)&Xs[c * 128 + tn * 4];
            float4 x1 = *(const float4*)&Xs[c * 128 + 64 + tn * 4];
            float ra[8] = {a0.x, a0.y, a0.z, a0.w, a1.x, a1.y, a1.z, a1.w};
            float rx[8] = {x0.x, x0.y, x0.z, x0.w, x1.x, x1.y, x1.z, x1.w};
#pragma unroll
            for (int i = 0; i < 8; i++)
#pragma unroll
                for (int j = 0; j < 8; j++) acc[i][j] += ra[i] * rx[j];
        }
        __syncthreads();
    }

#pragma unroll
    for (int i = 0; i < 8; i++) {
        int r = tr * 4 + (i & 3) + (i >> 2) * 64;
#pragma unroll
        for (int j = 0; j < 8; j++) {
            int n = n0 + tn * 4 + (j & 3) + (j >> 2) * 64;
            __half v = __float2half_rn(acc[i][j]);
            if (r < 64) {   // K A-frag pack
                int k = r, m = n;
                int mch = m >> 5, ml = m & 31, mi = ml >> 4, m16 = ml & 15;
                int kc = k >> 4, k16 = k & 15;
                int gg = m16 & 7, tt = (k16 & 7) >> 1, dlt = k16 & 1;
                int rr = (m16 >> 3) + ((k16 >> 3) << 1);
                int idx = (b * 32 + mch) * 2048
                        + ((kc * 2 + mi) * 32 + gg * 4 + tt) * 8 + rr * 2 + dlt;
                g_K[idx] = v;
            } else {        // V A-frag pack
                int vv = r - 64, m = n;
                int mch = m >> 5, ml = m & 31, s = ml >> 4, m16 = ml & 15;
                int vi = vv >> 4, v16 = vv & 15;
                int gg = v16 & 7, tt = (m16 & 7) >> 1, dlt = m16 & 1;
                int rr = (v16 >> 3) + ((m16 >> 3) << 1);
                int idx = (b * 32 + mch) * 2048
                        + ((s * 4 + vi) * 32 + gg * 4 + tt) * 8 + rr * 2 + dlt;
                g_V[idx] = v;
            }
        }
    }
}

// phase-1 logits: c1 = K_chunk^T x Q  (fp16 mma)
__device__ __forceinline__ void phase1(const __half* Ks,
                                       const uint32_t Qreg[4][4][2],
                                       float c1[2][4][4], int lane) {
#pragma unroll
    for (int kc = 0; kc < 4; kc++) {
        uint4 a0 = *(const uint4*)&Ks[(kc * 2 + 0) * 256 + lane * 8];
        uint4 a1 = *(const uint4*)&Ks[(kc * 2 + 1) * 256 + lane * 8];
#pragma unroll
        for (int ni = 0; ni < 4; ni++) {
            if (kc == 0) {
                mmaf16z(c1[0][ni], (const uint32_t*)&a0, Qreg[0][ni]);
                mmaf16z(c1[1][ni], (const uint32_t*)&a1, Qreg[0][ni]);
            } else {
                mmaf16(c1[0][ni], (const uint32_t*)&a0, Qreg[kc][ni]);
                mmaf16(c1[1][ni], (const uint32_t*)&a1, Qreg[kc][ni]);
            }
        }
    }
}

// ---------------- kernel 2: fused main (256 thr, fp16 operands) ----------------
__global__ void __launch_bounds__(256, 1) mqa_main(const float* __restrict__ x,
                                                   float* __restrict__ out) {
    extern __shared__ __half smh[];

    const int b = blockIdx.y;
    const int n0 = blockIdx.x * 32;
    const int tid = threadIdx.x;
    const int lane = tid & 31;
    const int wgrp = tid >> 5;   // 0..7
    const int gid = lane >> 2;
    const int tig = lane & 3;

    const __half* Kg = g_K + b * 65536;
    const __half* Vg = g_V + b * 65536;

    const uint32_t smem_u32 = (uint32_t)__cvta_generic_to_shared(smh);
#pragma unroll
    for (int s = 0; s < 4; s++) {
        uint32_t dst = smem_u32 + s * 8192 + tid * 16;
        cp16(dst, Kg + s * 2048 + tid * 8);
        cp16(dst + 4096, Vg + s * 2048 + tid * 8);
        CP_COMMIT();
    }

    // ---- prologue: Q projection (fp16 mma) ----
    uint32_t Qreg[4][4][2];
    {
        __half* Xs = smh + XS_OFF;   // [32 n][264 d]
        const float* Xb = x + b * (D * NN);
#pragma unroll
        for (int i = 0; i < 32; i++) {
            int idx = tid + i * 256;
            int dd = idx >> 5, nn2 = idx & 31;
            Xs[nn2 * XSP + dd] = __float2half_rn(Xb[dd * NN + n0 + nn2]);
        }
        __syncthreads();

        float qa[4][4][4] = {};
        const __half* WqPw = g_WqP + wgrp * 16384;
#pragma unroll 4
        for (int kc = 0; kc < 16; kc++) {
            uint32_t bf[4][2];
#pragma unroll
            for (int ni = 0; ni < 4; ni++) {
                bf[ni][0] = *(const uint32_t*)&Xs[(ni * 8 + gid) * XSP + kc * 16 + 2 * tig];
                bf[ni][1] = *(const uint32_t*)&Xs[(ni * 8 + gid) * XSP + kc * 16 + 2 * tig + 8];
            }
#pragma unroll
            for (int mi = 0; mi < 4; mi++) {
                uint4 a = *(const uint4*)&WqPw[(kc * 4 + mi) * 256 + lane * 8];
#pragma unroll
                for (int ni = 0; ni < 4; ni++)
                    mmaf16(qa[mi][ni], (const uint32_t*)&a, bf[ni]);
            }
        }
        __syncthreads();   // Xs reads done

        __half* Qsm = smh + QSM_OFF;   // [256 col][72 k]
#pragma unroll
        for (int mi = 0; mi < 4; mi++)
#pragma unroll
            for (int ni = 0; ni < 4; ni++)
#pragma unroll
                for (int r = 0; r < 4; r++) {
                    int rk = wgrp * 64 + mi * 16 + gid + 8 * (r >> 1);
                    int nl = ni * 8 + 2 * tig + (r & 1);
                    Qsm[(nl * 8 + (rk & 7)) * QSP2 + (rk >> 3)] =
                        __float2half_rn(qa[mi][ni][r]);
                }
        __syncthreads();

#pragma unroll
        for (int kc = 0; kc < 4; kc++)
#pragma unroll
            for (int ni = 0; ni < 4; ni++)
#pragma unroll
                for (int e = 0; e < 2; e++)
                    Qreg[kc][ni][e] = *(const uint32_t*)
                        &Qsm[(wgrp * 32 + ni * 8 + gid) * QSP2 + kc * 16 + 2 * tig + 8 * e];
    }

    // ---- stage 0 ready; phase1(0) ----
    CP_WAIT(3);
    __syncthreads();

    float c1[2][4][4];
    phase1(smh, Qreg, c1, lane);

    float Oacc[4][4][4] = {};
    const int srcA = 8 * tig + (gid >> 1);         // lane holding delta=0
    const uint32_t psel = (gid & 1) ? 0x7632u : 0x5410u;
    int sW = 4, sP1 = 1, sP3 = 0;

#pragma unroll 1
    for (int mch = 0; mch < 31; mch++) {
        CP_WAIT(2);
        __syncthreads();

        if (mch + 4 < 32) {
            uint32_t dst = smem_u32 + sW * 8192 + tid * 16;
            cp16(dst, Kg + (mch + 4) * 2048 + tid * 8);
            cp16(dst + 4096, Vg + (mch + 4) * 2048 + tid * 8);
        }
        CP_COMMIT();

        // ---- softmax over heads -> packed half2 C-frags ----
        uint32_t c1h[2][4][2];
#pragma unroll
        for (int mi = 0; mi < 2; mi++)
#pragma unroll
            for (int ni = 0; ni < 4; ni++) {
                float* cc = c1[mi][ni];
                float e0 = ex2(cc[0]), e1 = ex2(cc[1]);
                float sa = e0 + e1;
                sa += __shfl_xor_sync(0xffffffffu, sa, 1);
                sa += __shfl_xor_sync(0xffffffffu, sa, 2);
                float ra = rcp(sa);
                c1h[mi][ni][0] = packh2(e0 * ra, e1 * ra);
                float e2 = ex2(cc[2]), e3 = ex2(cc[3]);
                float sb = e2 + e3;
                sb += __shfl_xor_sync(0xffffffffu, sb, 1);
                sb += __shfl_xor_sync(0xffffffffu, sb, 2);
                float rb = rcp(sb);
                c1h[mi][ni][1] = packh2(e2 * rb, e3 * rb);
            }

        // ---- transpose C-frags -> fp16 B-frags (shfl + prmt) ----
        uint32_t bt[2][4][2];
#pragma unroll
        for (int s = 0; s < 2; s++)
#pragma unroll
            for (int ni = 0; ni < 4; ni++)
#pragma unroll
                for (int e = 0; e < 2; e++) {
                    uint32_t pA = __shfl_sync(0xffffffffu, c1h[s][ni][e], srcA);
                    uint32_t pB = __shfl_sync(0xffffffffu, c1h[s][ni][e], srcA + 4);
                    bt[s][ni][e] = prmtb(pA, pB, psel);
                }

        // ---- phase1 for chunk mch+1 (fills stall holes; c1 fully consumed) ----
        phase1(smh + sP1 * STAGE_H, Qreg, c1, lane);

        // ---- phase3: O += V @ attn (chunk mch) ----
        {
            const __half* Vs = smh + sP3 * STAGE_H + 2048;
#pragma unroll
            for (int s = 0; s < 2; s++)
#pragma unroll
                for (int vi = 0; vi < 4; vi++) {
                    uint4 av = *(const uint4*)&Vs[(s * 4 + vi) * 256 + lane * 8];
#pragma unroll
                    for (int ni = 0; ni < 4; ni++)
                        mmaf16(Oacc[vi][ni], (const uint32_t*)&av, bt[s][ni]);
                }
        }

        sW = (sW == NSTAGE - 1) ? 0 : sW + 1;
        sP1 = (sP1 == NSTAGE - 1) ? 0 : sP1 + 1;
        sP3 = (sP3 == NSTAGE - 1) ? 0 : sP3 + 1;
    }

    // ---- peeled final chunk ----
    {
        uint32_t c1h[2][4][2];
#pragma unroll
        for (int mi = 0; mi < 2; mi++)
#pragma unroll
            for (int ni = 0; ni < 4; ni++) {
                float* cc = c1[mi][ni];
                float e0 = ex2(cc[0]), e1 = ex2(cc[1]);
                float sa = e0 + e1;
                sa += __shfl_xor_sync(0xffffffffu, sa, 1);
                sa += __shfl_xor_sync(0xffffffffu, sa, 2);
                float ra = rcp(sa);
                c1h[mi][ni][0] = packh2(e0 * ra, e1 * ra);
                float e2 = ex2(cc[2]), e3 = ex2(cc[3]);
                float sb = e2 + e3;
                sb += __shfl_xor_sync(0xffffffffu, sb, 1);
                sb += __shfl_xor_sync(0xffffffffu, sb, 2);
                float rb = rcp(sb);
                c1h[mi][ni][1] = packh2(e2 * rb, e3 * rb);
            }
        const __half* Vs = smh + sP3 * STAGE_H + 2048;
#pragma unroll
        for (int s = 0; s < 2; s++) {
            uint32_t bt[4][2];
#pragma unroll
            for (int ni = 0; ni < 4; ni++)
#pragma unroll
                for (int e = 0; e < 2; e++) {
                    uint32_t pA = __shfl_sync(0xffffffffu, c1h[s][ni][e], srcA);
                    uint32_t pB = __shfl_sync(0xffffffffu, c1h[s][ni][e], srcA + 4);
                    bt[ni][e] = prmtb(pA, pB, psel);
                }
#pragma unroll
            for (int vi = 0; vi < 4; vi++) {
                uint4 av = *(const uint4*)&Vs[(s * 4 + vi) * 256 + lane * 8];
#pragma unroll
                for (int ni = 0; ni < 4; ni++)
                    mmaf16(Oacc[vi][ni], (const uint32_t*)&av, bt[ni]);
            }
        }
    }
    CP_WAIT(0);
    __syncthreads();

    // ---- epilogue: stage O as [n][vh] fp16 ----
    __half* Os = smh;   // [32][520]
#pragma unroll
    for (int vi = 0; vi < 4; vi++)
#pragma unroll
        for (int ni = 0; ni < 4; ni++) {
            int nl = wgrp * 4 + ni;
            int v = vi * 16 + gid;
            *(uint32_t*)&Os[nl * OSP + v * 8 + 2 * tig] =
                packh2(Oacc[vi][ni][0], Oacc[vi][ni][1]);
            *(uint32_t*)&Os[nl * OSP + (v + 8) * 8 + 2 * tig] =
                packh2(Oacc[vi][ni][2], Oacc[vi][ni][3]);
        }
    __syncthreads();

    // ---- res = Wo @ O (fp16 mma, Wo A-frags from gmem/L2) ----
    float racc[2][4][4] = {};
    const __half* WoP = g_WoP + wgrp * 16384;
#pragma unroll 2
    for (int ks = 0; ks < 32; ks++) {
        uint4 a0 = *(const uint4*)&WoP[(ks * 2 + 0) * 256 + lane * 8];
        uint4 a1 = *(const uint4*)&WoP[(ks * 2 + 1) * 256 + lane * 8];
#pragma unroll
        for (int ni = 0; ni < 4; ni++) {
            uint32_t bf[2];
            bf[0] = *(const uint32_t*)&Os[(ni * 8 + gid) * OSP + ks * 16 + 2 * tig];
            bf[1] = *(const uint32_t*)&Os[(ni * 8 + gid) * OSP + ks * 16 + 2 * tig + 8];
            mmaf16(racc[0][ni], (const uint32_t*)&a0, bf);
            mmaf16(racc[1][ni], (const uint32_t*)&a1, bf);
        }
    }

    float* ob = out + b * (D * NN);
#pragma unroll
    for (int mi = 0; mi < 2; mi++)
#pragma unroll
        for (int ni = 0; ni < 4; ni++) {
            int d = wgrp * 32 + mi * 16 + gid;
            *(float2*)&ob[d * NN + n0 + ni * 8 + tig * 2] =
                make_float2(racc[mi][ni][0], racc[mi][ni][1]);
            *(float2*)&ob[(d + 8) * NN + n0 + ni * 8 + tig * 2] =
                make_float2(racc[mi][ni][2], racc[mi][ni][3]);
        }
}

// ---------------- launcher ----------------
extern "C" void kernel_launch(void* const* d_in, const int* in_sizes, int n_in,
                              void* d_out, int out_size) {
    const float* x     = (const float*)d_in[0];
    const float* value = (const float*)d_in[1];
    const float* Wq    = (const float*)d_in[2];
    const float* Wk    = (const float*)d_in[3];
    const float* Wv    = (const float*)d_in[4];
    const float* Wo    = (const float*)d_in[5];
    float* out = (float*)d_out;

    pack_weights<<<512, 256>>>(Wq, Wk, Wv, Wo);
    proj_kv<<<dim3(MM / 128, 1, B), 256>>>(value);

    cudaFuncSetAttribute(mqa_main, cudaFuncAttributeMaxDynamicSharedMemorySize, SMEM_BYTES);
    mqa_main<<<dim3(NN / 32, B), 256, SMEM_BYTES>>>(x, out);
}

// round 11
// speedup vs baseline: 1.4582x; 1.0082x over previous
#include <cuda_runtime.h>
#include <cuda_fp16.h>
#include <math.h>
#include <stdint.h>

#define B 8
#define D 256
#define NN 1024
#define MM 1024
#define KD 64
#define VD 64
#define KVR 128

#define NSTAGE 5
// smem halves: stage = K(3072, padded) + V(2560, padded)
#define STAGE_H 5632
#define V_OFF   3072
#define STAGES_H (NSTAGE * STAGE_H)     // 28160
#define XS_OFF  STAGES_H
#define XSP 264                          // Xs [32 n][264 d]
#define QSM_OFF STAGES_H
#define KP 68                            // Qsm [32 nl][8 h][68 k]
#define SMEM_HALFS (QSM_OFF + 32 * 8 * KP)   // 45568
#define SMEM_BYTES (SMEM_HALFS * 2)           // 91136
#define OSP 520                          // epilogue Os [32 n][520 vh] @ 0

#define QSCALE 0.1803368801f   // 0.125 * log2(e)

__device__ float  g_WkvT[KVR * D];
__device__ __half g_WqP[512 * D];    // Wq A-frags fp16, pre-scaled
__device__ __half g_K[B * 32 * 2048];   // K as B-frags (k x m) per chunk
__device__ __half g_V[B * 32 * 2048];   // V as B-frags (m x v) per chunk
__device__ __half g_WoP[D * 512];    // Wo A-frags fp16

__device__ __forceinline__ float ex2(float x) {
    float r; asm("ex2.approx.f32 %0, %1;" : "=f"(r) : "f"(x)); return r;
}
__device__ __forceinline__ float rcp(float x) {
    float r; asm("rcp.approx.f32 %0, %1;" : "=f"(r) : "f"(x)); return r;
}
__device__ __forceinline__ uint32_t packh2(float a, float b) {
    __half2 h = __floats2half2_rn(a, b);
    return *reinterpret_cast<uint32_t*>(&h);
}
__device__ __forceinline__ void mmaf16(float* c, const uint32_t* a, const uint32_t* b) {
    asm volatile(
        "mma.sync.aligned.m16n8k16.row.col.f32.f16.f16.f32 "
        "{%0,%1,%2,%3}, {%4,%5,%6,%7}, {%8,%9}, {%0,%1,%2,%3};\n"
        : "+f"(c[0]), "+f"(c[1]), "+f"(c[2]), "+f"(c[3])
        : "r"(a[0]), "r"(a[1]), "r"(a[2]), "r"(a[3]), "r"(b[0]), "r"(b[1]));
}
__device__ __forceinline__ void mmaf16z(float* c, const uint32_t* a, const uint32_t* b) {
    asm volatile(
        "mma.sync.aligned.m16n8k16.row.col.f32.f16.f16.f32 "
        "{%0,%1,%2,%3}, {%4,%5,%6,%7}, {%8,%9}, {%10,%10,%10,%10};\n"
        : "=f"(c[0]), "=f"(c[1]), "=f"(c[2]), "=f"(c[3])
        : "r"(a[0]), "r"(a[1]), "r"(a[2]), "r"(a[3]), "r"(b[0]), "r"(b[1]),
          "f"(0.0f));
}
__device__ __forceinline__ void cp16(uint32_t dst, const void* src) {
    asm volatile("cp.async.cg.shared.global [%0], [%1], 16;\n"
                 :: "r"(dst), "l"(src));
}
#define CP_COMMIT() asm volatile("cp.async.commit_group;\n" ::)
#define CP_WAIT(n)  asm volatile("cp.async.wait_group %0;\n" :: "n"(n))

// ---------------- kernel 0: pack weights ----------------
__global__ void pack_weights(const float* __restrict__ Wq,
                             const float* __restrict__ Wk,
                             const float* __restrict__ Wv,
                             const float* __restrict__ Wo) {
    int i = blockIdx.x * blockDim.x + threadIdx.x;
    if (i < KVR * D) {
        int r = i / D, d = i % D;
        g_WkvT[i] = (r < 64) ? Wk[d * KD + r] : Wv[d * VD + (r - 64)];
    }
    if (i < 512 * D) {   // WqP: [w8][kc16][mi4][lane32][r4][dlt2]
        int dlt = i & 1, r = (i >> 1) & 3, ln = (i >> 3) & 31;
        int mi = (i >> 8) & 3, kc = (i >> 10) & 15, w = (i >> 14) & 7;
        int g = ln >> 2, t = ln & 3;
        int rk = w * 64 + mi * 16 + g + 8 * (r & 1);
        int d = kc * 16 + 2 * t + dlt + 8 * (r >> 1);
        int kq = rk >> 3, h = rk & 7;
        g_WqP[i] = __float2half_rn(Wq[h * (D * KD) + d * KD + kq] * QSCALE);
    }
    if (i < D * 512) {   // WoP: [w8][ks32][mi2][lane32][r4][dlt2]
        int dlt = i & 1, r = (i >> 1) & 3, ln = (i >> 3) & 31;
        int mi = (i >> 8) & 1, ks = (i >> 9) & 31, w = (i >> 14) & 7;
        int g = ln >> 2, t = ln & 3;
        int d = w * 32 + mi * 16 + g + 8 * (r & 1);
        int vh = ks * 16 + 2 * t + dlt + 8 * (r >> 1);
        g_WoP[i] = __float2half_rn(Wo[d * 512 + vh]);
    }
}

// ---------------- kernel 1: K/V projection GEMM (B-frag fp16 output) ----------------
__global__ void __launch_bounds__(256) proj_kv(const float* __restrict__ X) {
    const int b = blockIdx.z, n0 = blockIdx.x * 128;
    const float* A = g_WkvT;
    const float* Xb = X + b * (D * NN);

    __shared__ float As[16 * 136];
    __shared__ float Xs[16 * 128];

    float acc[8][8] = {};
    const int tid = threadIdx.x;
    const int tr = tid >> 4, tn = tid & 15;

    for (int dc = 0; dc < D; dc += 16) {
#pragma unroll
        for (int i = 0; i < 8; i++) {
            int idx = tid + i * 256;
            int rr = idx >> 4, c = idx & 15;
            As[c * 136 + rr] = A[rr * D + dc + c];
        }
#pragma unroll
        for (int i = 0; i < 8; i++) {
            int idx = tid + i * 256;
            int c = idx >> 7, nn = idx & 127;
            Xs[c * 128 + nn] = Xb[(dc + c) * NN + n0 + nn];
        }
        __syncthreads();
#pragma unroll
        for (int c = 0; c < 16; c++) {
            float4 a0 = *(const float4*)&As[c * 136 + tr * 4];
            float4 a1 = *(const float4*)&As[c * 136 + 64 + tr * 4];
            float4 x0 = *(const float4*)&Xs[c * 128 + tn * 4];
            float4 x1 = *(const float4*)&Xs[c * 128 + 64 + tn * 4];
            float ra[8] = {a0.x, a0.y, a0.z, a0.w, a1.x, a1.y, a1.z, a1.w};
            float rx[8] = {x0.x, x0.y, x0.z, x0.w, x1.x, x1.y, x1.z, x1.w};
#pragma unroll
            for (int i = 0; i < 8; i++)
#pragma unroll
                for (int j = 0; j < 8; j++) acc[i][j] += ra[i] * rx[j];
        }
        __syncthreads();
    }

#pragma unroll
    for (int i = 0; i < 8; i++) {
        int r = tr * 4 + (i & 3) + (i >> 2) * 64;
#pragma unroll
        for (int j = 0; j < 8; j++) {
            int n = n0 + tn * 4 + (j & 3) + (j >> 2) * 64;
            __half v = __float2half_rn(acc[i][j]);
            if (r < 64) {   // K B-frag pack: K[k][m], n-col = m
                int k = r, m = n;
                int mch = m >> 5, ml = m & 31;
                int nt = ml >> 3, gd = ml & 7;
                int ks = k >> 4, k16 = k & 15;
                int e = k16 >> 3, rem = k16 & 7, tg = rem >> 1, dlt = rem & 1;
                int ln = gd * 4 + tg;
                g_K[(b * 32 + mch) * 2048 + ks * 512 + ln * 16 + nt * 4 + e * 2 + dlt] = v;
            } else {        // V B-frag pack: V[m][v] with k-dim = m, n-col = v
                int vv = r - 64, m = n;
                int mch = m >> 5, ml = m & 31;
                int ms = ml >> 4, m16 = ml & 15;
                int e = m16 >> 3, rem = m16 & 7, tg = rem >> 1, dlt = rem & 1;
                int vt = vv >> 3, gd = vv & 7;
                int ln = gd * 4 + tg;
                g_V[(b * 32 + mch) * 2048 + ms * 1024 + ln * 32 + vt * 4 + e * 2 + dlt] = v;
            }
        }
    }
}

// phase-1: c1[mi][nt] = logits^T  (A = Q^T regs, B = K from smem)
__device__ __forceinline__ void phase1(const __half* Ks,
                                       const uint32_t Qreg[4][2][4],
                                       float c1[2][4][4], int lane) {
#pragma unroll
    for (int ks = 0; ks < 4; ks++) {
        uint4 ka = *(const uint4*)&Ks[ks * 768 + lane * 24];
        uint4 kb = *(const uint4*)&Ks[ks * 768 + lane * 24 + 8];
        uint32_t kf[4][2] = {{ka.x, ka.y}, {ka.z, ka.w}, {kb.x, kb.y}, {kb.z, kb.w}};
#pragma unroll
        for (int mi = 0; mi < 2; mi++)
#pragma unroll
            for (int nt = 0; nt < 4; nt++) {
                if (ks == 0) mmaf16z(c1[mi][nt], Qreg[0][mi], kf[nt]);
                else         mmaf16(c1[mi][nt], Qreg[ks][mi], kf[nt]);
            }
    }
}

// softmax over heads: rows r = (h&3) + 4*nl2 + 8*(h>>2); heads live in
// this lane's (c0,c2)/(c1,c3) plus lanes gid^1, gid^2 (lane xor 4, 8).
__device__ __forceinline__ void softmax_pack(float c1[2][4][4],
                                             uint32_t p01[2][4],
                                             uint32_t p23[2][4]) {
#pragma unroll
    for (int mi = 0; mi < 2; mi++)
#pragma unroll
        for (int nt = 0; nt < 4; nt++) {
            float* cc = c1[mi][nt];
            float e0 = ex2(cc[0]), e1 = ex2(cc[1]);
            float e2 = ex2(cc[2]), e3 = ex2(cc[3]);
            float s02 = e0 + e2, s13 = e1 + e3;
            s02 += __shfl_xor_sync(0xffffffffu, s02, 4);
            s02 += __shfl_xor_sync(0xffffffffu, s02, 8);
            s13 += __shfl_xor_sync(0xffffffffu, s13, 4);
            s13 += __shfl_xor_sync(0xffffffffu, s13, 8);
            float r02 = rcp(s02), r13 = rcp(s13);
            p01[mi][nt] = packh2(e0 * r02, e1 * r13);
            p23[mi][nt] = packh2(e2 * r02, e3 * r13);
        }
}

// phase-3: Oacc[mi][vt] += attn^T (A from packs) x V (B from smem)
__device__ __forceinline__ void phase3(const __half* Vs,
                                       const uint32_t p01[2][4],
                                       const uint32_t p23[2][4],
                                       float Oacc[2][8][4], int lane) {
#pragma unroll
    for (int ms = 0; ms < 2; ms++) {
        uint4 va = *(const uint4*)&Vs[ms * 1280 + lane * 40];
        uint4 vb = *(const uint4*)&Vs[ms * 1280 + lane * 40 + 8];
        uint4 vc = *(const uint4*)&Vs[ms * 1280 + lane * 40 + 16];
        uint4 vd = *(const uint4*)&Vs[ms * 1280 + lane * 40 + 24];
        uint32_t vf[8][2] = {{va.x, va.y}, {va.z, va.w}, {vb.x, vb.y}, {vb.z, vb.w},
                             {vc.x, vc.y}, {vc.z, vc.w}, {vd.x, vd.y}, {vd.z, vd.w}};
#pragma unroll
        for (int mi = 0; mi < 2; mi++) {
            uint32_t af[4] = {p01[mi][2 * ms], p23[mi][2 * ms],
                              p01[mi][2 * ms + 1], p23[mi][2 * ms + 1]};
#pragma unroll
            for (int vt = 0; vt < 8; vt++)
                mmaf16(Oacc[mi][vt], af, vf[vt]);
        }
    }
}

// ---------------- kernel 2: fused main ----------------
__global__ void __launch_bounds__(256, 1) mqa_main(const float* __restrict__ x,
                                                   float* __restrict__ out) {
    extern __shared__ __half smh[];

    const int b = blockIdx.y;
    const int n0 = blockIdx.x * 32;
    const int tid = threadIdx.x;
    const int lane = tid & 31;
    const int wgrp = tid >> 5;   // 0..7
    const int gid = lane >> 2;
    const int tig = lane & 3;

    const __half* Kg = g_K + b * 65536;
    const __half* Vg = g_V + b * 65536;

    // per-thread cp.async dst offsets (halves, padded layouts)
    const int dK = (tid >> 6) * 768 + ((tid & 63) >> 1) * 24 + (tid & 1) * 8;
    const int dV = V_OFF + (tid >> 7) * 1280 + ((tid >> 2) & 31) * 40 + (tid & 3) * 8;

    const uint32_t smem_u32 = (uint32_t)__cvta_generic_to_shared(smh);
#pragma unroll
    for (int s = 0; s < 4; s++) {
        cp16(smem_u32 + (s * STAGE_H + dK) * 2, Kg + s * 2048 + tid * 8);
        cp16(smem_u32 + (s * STAGE_H + dV) * 2, Vg + s * 2048 + tid * 8);
        CP_COMMIT();
    }

    // ---- prologue: Q projection (fp16 mma), then Q^T A-frags ----
    uint32_t Qreg[4][2][4];
    {
        __half* Xs = smh + XS_OFF;   // [32 n][264 d]
        const float* Xb = x + b * (D * NN);
#pragma unroll
        for (int i = 0; i < 32; i++) {
            int idx = tid + i * 256;
            int dd = idx >> 5, nn2 = idx & 31;
            Xs[nn2 * XSP + dd] = __float2half_rn(Xb[dd * NN + n0 + nn2]);
        }
        __syncthreads();

        float qa[4][4][4] = {};
        const __half* WqPw = g_WqP + wgrp * 16384;
#pragma unroll 4
        for (int kc = 0; kc < 16; kc++) {
            uint32_t bf[4][2];
#pragma unroll
            for (int ni = 0; ni < 4; ni++) {
                bf[ni][0] = *(const uint32_t*)&Xs[(ni * 8 + gid) * XSP + kc * 16 + 2 * tig];
                bf[ni][1] = *(const uint32_t*)&Xs[(ni * 8 + gid) * XSP + kc * 16 + 2 * tig + 8];
            }
#pragma unroll
            for (int mi = 0; mi < 4; mi++) {
                uint4 a = *(const uint4*)&WqPw[(kc * 4 + mi) * 256 + lane * 8];
#pragma unroll
                for (int ni = 0; ni < 4; ni++)
                    mmaf16(qa[mi][ni], (const uint32_t*)&a, bf[ni]);
            }
        }
        __syncthreads();   // Xs reads done

        __half* Qsm = smh + QSM_OFF;   // [nl32][h8][KP]
#pragma unroll
        for (int mi = 0; mi < 4; mi++)
#pragma unroll
            for (int ni = 0; ni < 4; ni++)
#pragma unroll
                for (int r = 0; r < 4; r++) {
                    int rk = wgrp * 64 + mi * 16 + gid + 8 * (r >> 1);
                    int nl = ni * 8 + 2 * tig + (r & 1);
                    Qsm[(nl * 8 + (rk & 7)) * KP + (rk >> 3)] =
                        __float2half_rn(qa[mi][ni][r]);
                }
        __syncthreads();

        // A-frags: row gid -> (nl2=(gid>>2), h=gid&3); row gid+8 -> h+4
#pragma unroll
        for (int ks = 0; ks < 4; ks++)
#pragma unroll
            for (int mi = 0; mi < 2; mi++) {
                int nlb = wgrp * 4 + 2 * mi + (gid >> 2);
                int r01 = (nlb * 8 + (gid & 3)) * KP;
                int r23 = (nlb * 8 + (gid & 3) + 4) * KP;
                int kk = ks * 16 + 2 * tig;
                Qreg[ks][mi][0] = *(const uint32_t*)&Qsm[r01 + kk];
                Qreg[ks][mi][1] = *(const uint32_t*)&Qsm[r23 + kk];
                Qreg[ks][mi][2] = *(const uint32_t*)&Qsm[r01 + kk + 8];
                Qreg[ks][mi][3] = *(const uint32_t*)&Qsm[r23 + kk + 8];
            }
    }

    // ---- stage 0 ready; phase1(0) ----
    CP_WAIT(3);
    __syncthreads();

    float c1[2][4][4];
    phase1(smh, Qreg, c1, lane);

    float Oacc[2][8][4] = {};
    int sW = 4, sP1 = 1, sP3 = 0;

#pragma unroll 1
    for (int mch = 0; mch < 31; mch++) {
        CP_WAIT(2);
        __syncthreads();

        if (mch + 4 < 32) {
            cp16(smem_u32 + (sW * STAGE_H + dK) * 2, Kg + (mch + 4) * 2048 + tid * 8);
            cp16(smem_u32 + (sW * STAGE_H + dV) * 2, Vg + (mch + 4) * 2048 + tid * 8);
        }
        CP_COMMIT();

        uint32_t p01[2][4], p23[2][4];
        softmax_pack(c1, p01, p23);

        // phase1 of next chunk fills the softmax stall holes (c1 consumed)
        phase1(smh + sP1 * STAGE_H, Qreg, c1, lane);

        phase3(smh + sP3 * STAGE_H + V_OFF, p01, p23, Oacc, lane);

        sW = (sW == NSTAGE - 1) ? 0 : sW + 1;
        sP1 = (sP1 == NSTAGE - 1) ? 0 : sP1 + 1;
        sP3 = (sP3 == NSTAGE - 1) ? 0 : sP3 + 1;
    }

    // peeled final chunk
    {
        uint32_t p01[2][4], p23[2][4];
        softmax_pack(c1, p01, p23);
        phase3(smh + sP3 * STAGE_H + V_OFF, p01, p23, Oacc, lane);
    }
    CP_WAIT(0);
    __syncthreads();

    // ---- epilogue: stage O^T C-frags into Os[n][vh] ----
    __half* Os = smh;   // [32][OSP]
#pragma unroll
    for (int mi = 0; mi < 2; mi++) {
        int nl = wgrp * 4 + 2 * mi + (gid >> 2);
        int hb = gid & 3;
#pragma unroll
        for (int vt = 0; vt < 8; vt++) {
            int v0 = vt * 8 + 2 * tig;
            Os[nl * OSP + v0 * 8 + hb]           = __float2half_rn(Oacc[mi][vt][0]);
            Os[nl * OSP + (v0 + 1) * 8 + hb]     = __float2half_rn(Oacc[mi][vt][1]);
            Os[nl * OSP + v0 * 8 + hb + 4]       = __float2half_rn(Oacc[mi][vt][2]);
            Os[nl * OSP + (v0 + 1) * 8 + hb + 4] = __float2half_rn(Oacc[mi][vt][3]);
        }
    }
    __syncthreads();

    // ---- res = Wo @ O (fp16 mma, Wo A-frags from gmem/L2) ----
    float racc[2][4][4] = {};
    const __half* WoP = g_WoP + wgrp * 16384;
#pragma unroll 2
    for (int ks = 0; ks < 32; ks++) {
        uint4 a0 = *(const uint4*)&WoP[(ks * 2 + 0) * 256 + lane * 8];
        uint4 a1 = *(const uint4*)&WoP[(ks * 2 + 1) * 256 + lane * 8];
#pragma unroll
        for (int ni = 0; ni < 4; ni++) {
            uint32_t bf[2];
            bf[0] = *(const uint32_t*)&Os[(ni * 8 + gid) * OSP + ks * 16 + 2 * tig];
            bf[1] = *(const uint32_t*)&Os[(ni * 8 + gid) * OSP + ks * 16 + 2 * tig + 8];
            mmaf16(racc[0][ni], (const uint32_t*)&a0, bf);
            mmaf16(racc[1][ni], (const uint32_t*)&a1, bf);
        }
    }

    float* ob = out + b * (D * NN);
#pragma unroll
    for (int mi = 0; mi < 2; mi++)
#pragma unroll
        for (int ni = 0; ni < 4; ni++) {
            int d = wgrp * 32 + mi * 16 + gid;
            *(float2*)&ob[d * NN + n0 + ni * 8 + tig * 2] =
                make_float2(racc[mi][ni][0], racc[mi][ni][1]);
            *(float2*)&ob[(d + 8) * NN + n0 + ni * 8 + tig * 2] =
                make_float2(racc[mi][ni][2], racc[mi][ni][3]);
        }
}

// ---------------- launcher ----------------
extern "C" void kernel_launch(void* const* d_in, const int* in_sizes, int n_in,
                              void* d_out, int out_size) {
    const float* x     = (const float*)d_in[0];
    const float* value = (const float*)d_in[1];
    const float* Wq    = (const float*)d_in[2];
    const float* Wk    = (const float*)d_in[3];
    const float* Wv    = (const float*)d_in[4];
    const float* Wo    = (const float*)d_in[5];
    float* out = (float*)d_out;

    pack_weights<<<512, 256>>>(Wq, Wk, Wv, Wo);
    proj_kv<<<dim3(MM / 128, 1, B), 256>>>(value);

    cudaFuncSetAttribute(mqa_main, cudaFuncAttributeMaxDynamicSharedMemorySize, SMEM_BYTES);
    mqa_main<<<dim3(NN / 32, B), 256, SMEM_BYTES>>>(x, out);
}